// round 1
// baseline (speedup 1.0000x reference)
#include <cuda_runtime.h>
#include <cstdint>

// Problem dims (fixed by the reference)
#define BB 2
#define LL 2048
#define DD 1024
#define HH 16
#define DH 64
#define MTOT (BB*LL)        // 4096

// -------- scratch (static device globals; no allocation allowed) --------
__device__ float g_qkv[(size_t)MTOT * 3 * DD];          // (B*L, 3072)
__device__ float g_q[(size_t)BB * HH * LL * DH];        // (b,h,l,d)
__device__ float g_k[(size_t)BB * HH * LL * DH];
__device__ float g_v[(size_t)BB * HH * LL * DH];
__device__ float g_o[(size_t)MTOT * DD];                // (b,l, h*64+d)

// ============================================================
// SGEMM: C[M][N] = A[M][K] * B[N][K]^T   (both inputs K-major)
// BM=BN=64, BK=16, 256 threads, 4x4 micro-tile per thread.
// ============================================================
#define BM 64
#define BN 64
#define BK 16

__global__ __launch_bounds__(256)
void sgemm_nt(const float* __restrict__ A, const float* __restrict__ B,
              float* __restrict__ C, int M, int N, int K) {
    __shared__ float As[BK][BM + 4];
    __shared__ float Bs[BK][BN + 4];

    const int tid  = threadIdx.x;
    const int tx   = tid & 15;          // n quad
    const int ty   = tid >> 4;          // m quad
    const int lcol = tid & 15;          // k within tile
    const int lrow = tid >> 4;          // row pass base
    const int m0 = blockIdx.y * BM;
    const int n0 = blockIdx.x * BN;

    float acc[4][4];
#pragma unroll
    for (int i = 0; i < 4; i++)
#pragma unroll
        for (int j = 0; j < 4; j++) acc[i][j] = 0.f;

    for (int k0 = 0; k0 < K; k0 += BK) {
#pragma unroll
        for (int p = 0; p < 4; p++) {
            int r = lrow + p * 16;
            As[lcol][r] = A[(size_t)(m0 + r) * K + k0 + lcol];
            Bs[lcol][r] = B[(size_t)(n0 + r) * K + k0 + lcol];
        }
        __syncthreads();
#pragma unroll
        for (int k = 0; k < BK; k++) {
            float4 a = *(const float4*)&As[k][ty * 4];
            float4 b = *(const float4*)&Bs[k][tx * 4];
            float av[4] = {a.x, a.y, a.z, a.w};
            float bv[4] = {b.x, b.y, b.z, b.w};
#pragma unroll
            for (int i = 0; i < 4; i++)
#pragma unroll
                for (int j = 0; j < 4; j++) acc[i][j] += av[i] * bv[j];
        }
        __syncthreads();
    }
#pragma unroll
    for (int i = 0; i < 4; i++) {
        float4 o = {acc[i][0], acc[i][1], acc[i][2], acc[i][3]};
        *(float4*)&C[(size_t)(m0 + ty * 4 + i) * N + n0 + tx * 4] = o;
    }
}

// ============================================================
// rmsnorm + RoPE + head split.  One warp per (b,l,h).
// q is pre-scaled by 1/sqrt(Dh)=0.125 here.
// ============================================================
__global__ __launch_bounds__(256)
void norm_rope_split(const float* __restrict__ qkv, const float* __restrict__ rope,
                     const float* __restrict__ qw, const float* __restrict__ kw,
                     float* __restrict__ Q, float* __restrict__ K, float* __restrict__ V) {
    const int warp = (blockIdx.x * blockDim.x + threadIdx.x) >> 5;
    const int lane = threadIdx.x & 31;
    const int h  = warp & (HH - 1);
    const int bl = warp >> 4;               // b*L + l
    const int l  = bl & (LL - 1);
    const int b  = bl >> 11;

    const float* base = qkv + (size_t)bl * (3 * DD);
    const float c = rope[l * DH + lane * 2];
    const float s = rope[l * DH + lane * 2 + 1];
    const size_t obase = ((size_t)(b * HH + h) * LL + l) * DH;

    // ---- Q ----
    {
        float2 x = *(const float2*)(base + h * DH + lane * 2);
        float ss = x.x * x.x + x.y * x.y;
#pragma unroll
        for (int o = 16; o; o >>= 1) ss += __shfl_xor_sync(0xffffffffu, ss, o);
        float inv = rsqrtf(ss * (1.f / DH) + 1e-6f);
        float e = x.x * inv * qw[lane * 2];
        float o_ = x.y * inv * qw[lane * 2 + 1];
        Q[obase + lane * 2]     = 0.125f * (e * c - o_ * s);
        Q[obase + lane * 2 + 1] = 0.125f * (e * s + o_ * c);
    }
    // ---- K ----
    {
        float2 x = *(const float2*)(base + DD + h * DH + lane * 2);
        float ss = x.x * x.x + x.y * x.y;
#pragma unroll
        for (int o = 16; o; o >>= 1) ss += __shfl_xor_sync(0xffffffffu, ss, o);
        float inv = rsqrtf(ss * (1.f / DH) + 1e-6f);
        float e = x.x * inv * kw[lane * 2];
        float o_ = x.y * inv * kw[lane * 2 + 1];
        K[obase + lane * 2]     = e * c - o_ * s;
        K[obase + lane * 2 + 1] = e * s + o_ * c;
    }
    // ---- V copy ----
    {
        float2 v = *(const float2*)(base + 2 * DD + h * DH + lane * 2);
        *(float2*)&V[obase + lane * 2] = v;
    }
}

// ============================================================
// Flash attention: one block per (bh, q-tile of 64 rows),
// 64 threads, one q row per thread. K/V share one smem buffer
// (two-phase per kv tile); scores staged in smem.
// Output written directly in (b, l, h*64+d) layout.
// ============================================================
__global__ __launch_bounds__(64)
void attn_kernel(const float* __restrict__ Qg, const float* __restrict__ Kg,
                 const float* __restrict__ Vg, float* __restrict__ O) {
    __shared__ float KV[64][68];
    __shared__ float Ss[64][65];

    const int r  = threadIdx.x;                 // q row within tile
    const int bh = blockIdx.y;                  // 0..31
    const int lq = blockIdx.x * 64 + r;

    const float* qp = Qg + ((size_t)bh * LL + lq) * DH;
    float q[DH];
#pragma unroll
    for (int d = 0; d < DH; d += 4) {
        float4 t = *(const float4*)(qp + d);
        q[d] = t.x; q[d + 1] = t.y; q[d + 2] = t.z; q[d + 3] = t.w;
    }

    float acc[DH];
#pragma unroll
    for (int d = 0; d < DH; d++) acc[d] = 0.f;
    float m = -1e30f, lsum = 0.f;

    for (int kt = 0; kt < LL / 64; kt++) {
        __syncthreads();   // previous tile's V reads done before overwrite
        const float* kp = Kg + ((size_t)bh * LL + kt * 64 + r) * DH;
#pragma unroll
        for (int d = 0; d < DH; d += 4)
            *(float4*)&KV[r][d] = *(const float4*)(kp + d);
        __syncthreads();

        float mt = -1e30f;
#pragma unroll 4
        for (int j = 0; j < 64; j++) {
            float sacc = 0.f;
#pragma unroll
            for (int d = 0; d < DH; d += 4) {
                float4 kk = *(const float4*)&KV[j][d];
                sacc += q[d] * kk.x + q[d + 1] * kk.y + q[d + 2] * kk.z + q[d + 3] * kk.w;
            }
            Ss[r][j] = sacc;
            mt = fmaxf(mt, sacc);
        }
        __syncthreads();   // all dots done before K -> V overwrite

        const float* vp = Vg + ((size_t)bh * LL + kt * 64 + r) * DH;
#pragma unroll
        for (int d = 0; d < DH; d += 4)
            *(float4*)&KV[r][d] = *(const float4*)(vp + d);
        __syncthreads();

        float mnew  = fmaxf(m, mt);
        float alpha = __expf(m - mnew);
        lsum *= alpha;
#pragma unroll
        for (int d = 0; d < DH; d++) acc[d] *= alpha;

#pragma unroll 2
        for (int j = 0; j < 64; j++) {
            float p = __expf(Ss[r][j] - mnew);
            lsum += p;
#pragma unroll
            for (int d = 0; d < DH; d += 4) {
                float4 vv = *(const float4*)&KV[j][d];
                acc[d]     += p * vv.x;
                acc[d + 1] += p * vv.y;
                acc[d + 2] += p * vv.z;
                acc[d + 3] += p * vv.w;
            }
        }
        m = mnew;
    }

    const float invl = 1.f / lsum;
    const int b = bh >> 4, h = bh & (HH - 1);
    float* op = O + ((size_t)(b * LL + lq)) * DD + h * DH;
#pragma unroll
    for (int d = 0; d < DH; d += 4) {
        float4 o = {acc[d] * invl, acc[d + 1] * invl, acc[d + 2] * invl, acc[d + 3] * invl};
        *(float4*)(op + d) = o;
    }
}

// ============================================================
extern "C" void kernel_launch(void* const* d_in, const int* in_sizes, int n_in,
                              void* d_out, int out_size) {
    const float* x      = (const float*)d_in[0];
    const float* rope   = (const float*)d_in[1];
    const float* w_qkv  = (const float*)d_in[2];
    const float* w_proj = (const float*)d_in[3];
    const float* qw     = (const float*)d_in[4];
    const float* kw     = (const float*)d_in[5];
    float* out = (float*)d_out;

    float *qkv, *Q, *K, *V, *O;
    cudaGetSymbolAddress((void**)&qkv, g_qkv);
    cudaGetSymbolAddress((void**)&Q, g_q);
    cudaGetSymbolAddress((void**)&K, g_k);
    cudaGetSymbolAddress((void**)&V, g_v);
    cudaGetSymbolAddress((void**)&O, g_o);

    // 1) qkv = x @ w_qkv^T : (4096 x 1024) * (3072 x 1024)^T
    sgemm_nt<<<dim3(3 * DD / BN, MTOT / BM), 256>>>(x, w_qkv, qkv, MTOT, 3 * DD, DD);

    // 2) rmsnorm + rope + head split (q pre-scaled by 0.125)
    norm_rope_split<<<(MTOT * HH) / 8, 256>>>(qkv, rope, qw, kw, Q, K, V);

    // 3) attention -> g_o in (b,l,h*64+d) layout
    attn_kernel<<<dim3(LL / 64, BB * HH), 64>>>(Q, K, V, O);

    // 4) out = O @ w_proj^T : (4096 x 1024) * (1024 x 1024)^T
    sgemm_nt<<<dim3(DD / BN, MTOT / BM), 256>>>(O, w_proj, out, MTOT, DD, DD);
}

// round 2
// speedup vs baseline: 1.1648x; 1.1648x over previous
#include <cuda_runtime.h>
#include <cstdint>

// Problem dims (fixed by the reference)
#define BB 2
#define LL 2048
#define DD 1024
#define HH 16
#define DH 64
#define MTOT (BB*LL)        // 4096

typedef unsigned long long ull;

// ---------------- f32x2 packed helpers (sm_103a) ----------------
__device__ __forceinline__ ull pk2(float lo, float hi) {
    ull r; asm("mov.b64 %0, {%1, %2};" : "=l"(r) : "f"(lo), "f"(hi)); return r;
}
__device__ __forceinline__ void upk2(ull v, float& lo, float& hi) {
    asm("mov.b64 {%0, %1}, %2;" : "=f"(lo), "=f"(hi) : "l"(v));
}
__device__ __forceinline__ ull fma2(ull a, ull b, ull c) {
    ull r; asm("fma.rn.f32x2 %0, %1, %2, %3;" : "=l"(r) : "l"(a), "l"(b), "l"(c)); return r;
}
__device__ __forceinline__ ull mul2(ull a, ull b) {
    ull r; asm("mul.rn.f32x2 %0, %1, %2;" : "=l"(r) : "l"(a), "l"(b)); return r;
}
__device__ __forceinline__ ull add2(ull a, ull b) {
    ull r; asm("add.rn.f32x2 %0, %1, %2;" : "=l"(r) : "l"(a), "l"(b)); return r;
}

// -------- scratch (static device globals; no allocation allowed) --------
__device__ float g_qkv[(size_t)MTOT * 3 * DD];          // (B*L, 3072)
__device__ float g_q[(size_t)BB * HH * LL * DH];        // (b,h,l,d)
__device__ float g_k[(size_t)BB * HH * LL * DH];
__device__ float g_v[(size_t)BB * HH * LL * DH];
__device__ float g_o[(size_t)MTOT * DD];                // (b,l, h*64+d)

// ============================================================
// SGEMM: C[M][N] = A[M][K] * B[N][K]^T  (both K-major), f32x2.
// 128x128x16 tile, 256 threads, 8x8 microtile as 2x2 blocks of
// 4x4 (tx*4 and 64+tx*4 addressing -> conflict-free LDS.128).
// Register prefetch of next global tile.
// ============================================================
#define GBM 128
#define GBN 128
#define GBK 16
#define GPAD 4   // row stride 132 floats = 528B, 16B aligned

__global__ __launch_bounds__(256)
void sgemm_nt_f2(const float* __restrict__ A, const float* __restrict__ B,
                 float* __restrict__ C, int M, int N, int K) {
    __shared__ float As[GBK][GBM + GPAD];
    __shared__ float Bs[GBK][GBN + GPAD];

    const int tid = threadIdx.x;
    const int tx = tid & 15;        // n quad
    const int ty = tid >> 4;        // m quad
    const int lr = tid >> 1;        // load row 0..127
    const int lk = (tid & 1) * 8;   // load k offset 0/8
    const int m0 = blockIdx.y * GBM;
    const int n0 = blockIdx.x * GBN;

    ull acc[2][4][2][2];
#pragma unroll
    for (int rb = 0; rb < 2; rb++)
#pragma unroll
        for (int i = 0; i < 4; i++)
#pragma unroll
            for (int cb = 0; cb < 2; cb++) {
                acc[rb][i][cb][0] = 0ull; acc[rb][i][cb][1] = 0ull;
            }

    const float* aptr = A + (size_t)(m0 + lr) * K + lk;
    const float* bptr = B + (size_t)(n0 + lr) * K + lk;

    float4 pa0 = *(const float4*)(aptr);
    float4 pa1 = *(const float4*)(aptr + 4);
    float4 pb0 = *(const float4*)(bptr);
    float4 pb1 = *(const float4*)(bptr + 4);

    for (int k0 = 0; k0 < K; k0 += GBK) {
        // stage prefetched tile into smem (transposed)
        As[lk + 0][lr] = pa0.x; As[lk + 1][lr] = pa0.y;
        As[lk + 2][lr] = pa0.z; As[lk + 3][lr] = pa0.w;
        As[lk + 4][lr] = pa1.x; As[lk + 5][lr] = pa1.y;
        As[lk + 6][lr] = pa1.z; As[lk + 7][lr] = pa1.w;
        Bs[lk + 0][lr] = pb0.x; Bs[lk + 1][lr] = pb0.y;
        Bs[lk + 2][lr] = pb0.z; Bs[lk + 3][lr] = pb0.w;
        Bs[lk + 4][lr] = pb1.x; Bs[lk + 5][lr] = pb1.y;
        Bs[lk + 6][lr] = pb1.z; Bs[lk + 7][lr] = pb1.w;
        __syncthreads();

        if (k0 + GBK < K) {
            const float* ap = aptr + k0 + GBK;
            const float* bp = bptr + k0 + GBK;
            pa0 = *(const float4*)(ap);
            pa1 = *(const float4*)(ap + 4);
            pb0 = *(const float4*)(bp);
            pb1 = *(const float4*)(bp + 4);
        }

#pragma unroll
        for (int k = 0; k < GBK; k++) {
            float4 a0v = *(const float4*)&As[k][ty * 4];
            float4 a1v = *(const float4*)&As[k][64 + ty * 4];
            ulonglong2 b0v = *(const ulonglong2*)&Bs[k][tx * 4];
            ulonglong2 b1v = *(const ulonglong2*)&Bs[k][64 + tx * 4];
            ull bp_[2][2] = {{b0v.x, b0v.y}, {b1v.x, b1v.y}};
            float am[2][4] = {{a0v.x, a0v.y, a0v.z, a0v.w},
                              {a1v.x, a1v.y, a1v.z, a1v.w}};
#pragma unroll
            for (int rb = 0; rb < 2; rb++)
#pragma unroll
                for (int i = 0; i < 4; i++) {
                    ull ai = pk2(am[rb][i], am[rb][i]);
#pragma unroll
                    for (int cb = 0; cb < 2; cb++) {
                        acc[rb][i][cb][0] = fma2(ai, bp_[cb][0], acc[rb][i][cb][0]);
                        acc[rb][i][cb][1] = fma2(ai, bp_[cb][1], acc[rb][i][cb][1]);
                    }
                }
        }
        __syncthreads();
    }

#pragma unroll
    for (int rb = 0; rb < 2; rb++)
#pragma unroll
        for (int i = 0; i < 4; i++) {
            int row = m0 + rb * 64 + ty * 4 + i;
#pragma unroll
            for (int cb = 0; cb < 2; cb++) {
                float4 o;
                upk2(acc[rb][i][cb][0], o.x, o.y);
                upk2(acc[rb][i][cb][1], o.z, o.w);
                *(float4*)&C[(size_t)row * N + n0 + cb * 64 + tx * 4] = o;
            }
        }
}

// ============================================================
// rmsnorm + RoPE + head split.  One warp per (b,l,h).
// q is pre-scaled by 1/sqrt(Dh)=0.125 here.
// ============================================================
__global__ __launch_bounds__(256)
void norm_rope_split(const float* __restrict__ qkv, const float* __restrict__ rope,
                     const float* __restrict__ qw, const float* __restrict__ kw,
                     float* __restrict__ Q, float* __restrict__ K, float* __restrict__ V) {
    const int warp = (blockIdx.x * blockDim.x + threadIdx.x) >> 5;
    const int lane = threadIdx.x & 31;
    const int h  = warp & (HH - 1);
    const int bl = warp >> 4;               // b*L + l
    const int l  = bl & (LL - 1);
    const int b  = bl >> 11;

    const float* base = qkv + (size_t)bl * (3 * DD);
    const float c = rope[l * DH + lane * 2];
    const float s = rope[l * DH + lane * 2 + 1];
    const size_t obase = ((size_t)(b * HH + h) * LL + l) * DH;

    // ---- Q ----
    {
        float2 x = *(const float2*)(base + h * DH + lane * 2);
        float ss = x.x * x.x + x.y * x.y;
#pragma unroll
        for (int o = 16; o; o >>= 1) ss += __shfl_xor_sync(0xffffffffu, ss, o);
        float inv = rsqrtf(ss * (1.f / DH) + 1e-6f);
        float e = x.x * inv * qw[lane * 2];
        float o_ = x.y * inv * qw[lane * 2 + 1];
        Q[obase + lane * 2]     = 0.125f * (e * c - o_ * s);
        Q[obase + lane * 2 + 1] = 0.125f * (e * s + o_ * c);
    }
    // ---- K ----
    {
        float2 x = *(const float2*)(base + DD + h * DH + lane * 2);
        float ss = x.x * x.x + x.y * x.y;
#pragma unroll
        for (int o = 16; o; o >>= 1) ss += __shfl_xor_sync(0xffffffffu, ss, o);
        float inv = rsqrtf(ss * (1.f / DH) + 1e-6f);
        float e = x.x * inv * kw[lane * 2];
        float o_ = x.y * inv * kw[lane * 2 + 1];
        K[obase + lane * 2]     = e * c - o_ * s;
        K[obase + lane * 2 + 1] = e * s + o_ * c;
    }
    // ---- V copy ----
    {
        float2 v = *(const float2*)(base + 2 * DD + h * DH + lane * 2);
        *(float2*)&V[obase + lane * 2] = v;
    }
}

// ============================================================
// Flash attention with f32x2 packed math.
// One block per (bh, q-tile of 64 rows), 64 threads,
// one q row per thread. K/V share one smem buffer.
// ============================================================
__global__ __launch_bounds__(64)
void attn_kernel(const float* __restrict__ Qg, const float* __restrict__ Kg,
                 const float* __restrict__ Vg, float* __restrict__ O) {
    __shared__ float KV[64][68];   // 272B row stride, 16B aligned
    __shared__ float Ss[64][65];

    const int r  = threadIdx.x;                 // q row within tile
    const int bh = blockIdx.y;                  // 0..31
    const int lq = blockIdx.x * 64 + r;

    const float* qp = Qg + ((size_t)bh * LL + lq) * DH;
    ull q2[32];
    {
        const ulonglong2* qp2 = (const ulonglong2*)qp;
#pragma unroll
        for (int t = 0; t < 16; t++) {
            ulonglong2 v = qp2[t];
            q2[2 * t] = v.x; q2[2 * t + 1] = v.y;
        }
    }

    ull acc2[32];
#pragma unroll
    for (int i = 0; i < 32; i++) acc2[i] = 0ull;
    float m = -1e30f, lsum = 0.f;

    for (int kt = 0; kt < LL / 64; kt++) {
        __syncthreads();   // previous tile's V reads done before overwrite
        const float* kp = Kg + ((size_t)bh * LL + kt * 64 + r) * DH;
#pragma unroll
        for (int d = 0; d < DH; d += 4)
            *(float4*)&KV[r][d] = *(const float4*)(kp + d);
        __syncthreads();

        float mt = -1e30f;
#pragma unroll 2
        for (int j = 0; j < 64; j++) {
            const ulonglong2* kj = (const ulonglong2*)&KV[j][0];
            ull aa0 = 0ull, aa1 = 0ull, aa2 = 0ull, aa3 = 0ull;
#pragma unroll
            for (int t = 0; t < 16; t += 2) {
                ulonglong2 k0 = kj[t];
                ulonglong2 k1 = kj[t + 1];
                aa0 = fma2(q2[2 * t],     k0.x, aa0);
                aa1 = fma2(q2[2 * t + 1], k0.y, aa1);
                aa2 = fma2(q2[2 * t + 2], k1.x, aa2);
                aa3 = fma2(q2[2 * t + 3], k1.y, aa3);
            }
            ull tot = add2(add2(aa0, aa1), add2(aa2, aa3));
            float lo, hi; upk2(tot, lo, hi);
            float sacc = lo + hi;
            Ss[r][j] = sacc;
            mt = fmaxf(mt, sacc);
        }
        __syncthreads();   // all dots done before K -> V overwrite

        const float* vp = Vg + ((size_t)bh * LL + kt * 64 + r) * DH;
#pragma unroll
        for (int d = 0; d < DH; d += 4)
            *(float4*)&KV[r][d] = *(const float4*)(vp + d);
        __syncthreads();

        float mnew  = fmaxf(m, mt);
        float alpha = __expf(m - mnew);
        lsum *= alpha;
        ull av = pk2(alpha, alpha);
#pragma unroll
        for (int i = 0; i < 32; i++) acc2[i] = mul2(acc2[i], av);

#pragma unroll 2
        for (int j = 0; j < 64; j++) {
            float p = __expf(Ss[r][j] - mnew);
            lsum += p;
            ull pp = pk2(p, p);
            const ulonglong2* vj = (const ulonglong2*)&KV[j][0];
#pragma unroll
            for (int t = 0; t < 16; t++) {
                ulonglong2 vv = vj[t];
                acc2[2 * t]     = fma2(pp, vv.x, acc2[2 * t]);
                acc2[2 * t + 1] = fma2(pp, vv.y, acc2[2 * t + 1]);
            }
        }
        m = mnew;
    }

    const float invl = 1.f / lsum;
    const ull iv = pk2(invl, invl);
    const int b = bh >> 4, h = bh & (HH - 1);
    float* op = O + ((size_t)(b * LL + lq)) * DD + h * DH;
#pragma unroll
    for (int t = 0; t < 16; t++) {
        ulonglong2 o;
        o.x = mul2(acc2[2 * t], iv);
        o.y = mul2(acc2[2 * t + 1], iv);
        *(ulonglong2*)(op + 4 * t) = o;
    }
}

// ============================================================
extern "C" void kernel_launch(void* const* d_in, const int* in_sizes, int n_in,
                              void* d_out, int out_size) {
    const float* x      = (const float*)d_in[0];
    const float* rope   = (const float*)d_in[1];
    const float* w_qkv  = (const float*)d_in[2];
    const float* w_proj = (const float*)d_in[3];
    const float* qw     = (const float*)d_in[4];
    const float* kw     = (const float*)d_in[5];
    float* out = (float*)d_out;

    float *qkv, *Q, *K, *V, *O;
    cudaGetSymbolAddress((void**)&qkv, g_qkv);
    cudaGetSymbolAddress((void**)&Q, g_q);
    cudaGetSymbolAddress((void**)&K, g_k);
    cudaGetSymbolAddress((void**)&V, g_v);
    cudaGetSymbolAddress((void**)&O, g_o);

    // 1) qkv = x @ w_qkv^T : (4096 x 1024) * (3072 x 1024)^T
    sgemm_nt_f2<<<dim3(3 * DD / GBN, MTOT / GBM), 256>>>(x, w_qkv, qkv, MTOT, 3 * DD, DD);

    // 2) rmsnorm + rope + head split (q pre-scaled by 0.125)
    norm_rope_split<<<(MTOT * HH) / 8, 256>>>(qkv, rope, qw, kw, Q, K, V);

    // 3) attention -> g_o in (b,l,h*64+d) layout
    attn_kernel<<<dim3(LL / 64, BB * HH), 64>>>(Q, K, V, O);

    // 4) out = O @ w_proj^T : (4096 x 1024) * (1024 x 1024)^T
    sgemm_nt_f2<<<dim3(DD / GBN, MTOT / GBM), 256>>>(O, w_proj, out, MTOT, DD, DD);
}

// round 5
// speedup vs baseline: 1.5622x; 1.3412x over previous
#include <cuda_runtime.h>
#include <cstdint>

// Problem dims (fixed by the reference)
#define BB 2
#define LL 2048
#define DD 1024
#define HH 16
#define DH 64
#define MTOT (BB*LL)        // 4096

typedef unsigned long long ull;

// ---------------- f32x2 packed helpers (sm_103a) ----------------
__device__ __forceinline__ ull pk2(float lo, float hi) {
    ull r; asm("mov.b64 %0, {%1, %2};" : "=l"(r) : "f"(lo), "f"(hi)); return r;
}
__device__ __forceinline__ void upk2(ull v, float& lo, float& hi) {
    asm("mov.b64 {%0, %1}, %2;" : "=f"(lo), "=f"(hi) : "l"(v));
}
__device__ __forceinline__ ull fma2(ull a, ull b, ull c) {
    ull r; asm("fma.rn.f32x2 %0, %1, %2, %3;" : "=l"(r) : "l"(a), "l"(b), "l"(c)); return r;
}

// ---------------- tf32 mma helpers (sm_80+ base target) ----------------
__device__ __forceinline__ uint32_t tf32bits(float f) {
    uint32_t r; asm("cvt.rna.tf32.f32 %0, %1;" : "=r"(r) : "f"(f)); return r;
}
__device__ __forceinline__ float tf32f(float f) {
    return __uint_as_float(tf32bits(f));
}
__device__ __forceinline__ void mma_tf32(float c[4], const uint32_t a[4],
                                         uint32_t b0, uint32_t b1) {
    asm volatile(
        "mma.sync.aligned.m16n8k8.row.col.f32.tf32.tf32.f32 "
        "{%0,%1,%2,%3}, {%4,%5,%6,%7}, {%8,%9}, {%0,%1,%2,%3};"
        : "+f"(c[0]), "+f"(c[1]), "+f"(c[2]), "+f"(c[3])
        : "r"(a[0]), "r"(a[1]), "r"(a[2]), "r"(a[3]), "r"(b0), "r"(b1));
}

// -------- scratch (static device globals; no allocation allowed) --------
__device__ float g_qkv[(size_t)MTOT * 3 * DD];          // (B*L, 3072)
__device__ float g_q[(size_t)BB * HH * LL * DH];        // (b,h,l,d)
__device__ float g_k[(size_t)BB * HH * LL * DH];
__device__ float g_v[(size_t)BB * HH * LL * DH];        // TRANSPOSED: (b,h,d,l)
__device__ float g_o[(size_t)MTOT * DD];                // (b,l, h*64+d)

// ============================================================
// SGEMM: C[M][N] = A[M][K] * B[N][K]^T  (both K-major), f32x2.
// (proven round-2 kernel, unchanged)
// ============================================================
#define GBM 128
#define GBN 128
#define GBK 16
#define GPAD 4

__global__ __launch_bounds__(256)
void sgemm_nt_f2(const float* __restrict__ A, const float* __restrict__ B,
                 float* __restrict__ C, int M, int N, int K) {
    __shared__ float As[GBK][GBM + GPAD];
    __shared__ float Bs[GBK][GBN + GPAD];

    const int tid = threadIdx.x;
    const int tx = tid & 15;
    const int ty = tid >> 4;
    const int lr = tid >> 1;
    const int lk = (tid & 1) * 8;
    const int m0 = blockIdx.y * GBM;
    const int n0 = blockIdx.x * GBN;

    ull acc[2][4][2][2];
#pragma unroll
    for (int rb = 0; rb < 2; rb++)
#pragma unroll
        for (int i = 0; i < 4; i++)
#pragma unroll
            for (int cb = 0; cb < 2; cb++) {
                acc[rb][i][cb][0] = 0ull; acc[rb][i][cb][1] = 0ull;
            }

    const float* aptr = A + (size_t)(m0 + lr) * K + lk;
    const float* bptr = B + (size_t)(n0 + lr) * K + lk;

    float4 pa0 = *(const float4*)(aptr);
    float4 pa1 = *(const float4*)(aptr + 4);
    float4 pb0 = *(const float4*)(bptr);
    float4 pb1 = *(const float4*)(bptr + 4);

    for (int k0 = 0; k0 < K; k0 += GBK) {
        As[lk + 0][lr] = pa0.x; As[lk + 1][lr] = pa0.y;
        As[lk + 2][lr] = pa0.z; As[lk + 3][lr] = pa0.w;
        As[lk + 4][lr] = pa1.x; As[lk + 5][lr] = pa1.y;
        As[lk + 6][lr] = pa1.z; As[lk + 7][lr] = pa1.w;
        Bs[lk + 0][lr] = pb0.x; Bs[lk + 1][lr] = pb0.y;
        Bs[lk + 2][lr] = pb0.z; Bs[lk + 3][lr] = pb0.w;
        Bs[lk + 4][lr] = pb1.x; Bs[lk + 5][lr] = pb1.y;
        Bs[lk + 6][lr] = pb1.z; Bs[lk + 7][lr] = pb1.w;
        __syncthreads();

        if (k0 + GBK < K) {
            const float* ap = aptr + k0 + GBK;
            const float* bp = bptr + k0 + GBK;
            pa0 = *(const float4*)(ap);
            pa1 = *(const float4*)(ap + 4);
            pb0 = *(const float4*)(bp);
            pb1 = *(const float4*)(bp + 4);
        }

#pragma unroll
        for (int k = 0; k < GBK; k++) {
            float4 a0v = *(const float4*)&As[k][ty * 4];
            float4 a1v = *(const float4*)&As[k][64 + ty * 4];
            ulonglong2 b0v = *(const ulonglong2*)&Bs[k][tx * 4];
            ulonglong2 b1v = *(const ulonglong2*)&Bs[k][64 + tx * 4];
            ull bp_[2][2] = {{b0v.x, b0v.y}, {b1v.x, b1v.y}};
            float am[2][4] = {{a0v.x, a0v.y, a0v.z, a0v.w},
                              {a1v.x, a1v.y, a1v.z, a1v.w}};
#pragma unroll
            for (int rb = 0; rb < 2; rb++)
#pragma unroll
                for (int i = 0; i < 4; i++) {
                    ull ai = pk2(am[rb][i], am[rb][i]);
#pragma unroll
                    for (int cb = 0; cb < 2; cb++) {
                        acc[rb][i][cb][0] = fma2(ai, bp_[cb][0], acc[rb][i][cb][0]);
                        acc[rb][i][cb][1] = fma2(ai, bp_[cb][1], acc[rb][i][cb][1]);
                    }
                }
        }
        __syncthreads();
    }

#pragma unroll
    for (int rb = 0; rb < 2; rb++)
#pragma unroll
        for (int i = 0; i < 4; i++) {
            int row = m0 + rb * 64 + ty * 4 + i;
#pragma unroll
            for (int cb = 0; cb < 2; cb++) {
                float4 o;
                upk2(acc[rb][i][cb][0], o.x, o.y);
                upk2(acc[rb][i][cb][1], o.z, o.w);
                *(float4*)&C[(size_t)row * N + n0 + cb * 64 + tx * 4] = o;
            }
        }
}

// ============================================================
// rmsnorm + RoPE + head split.  One warp per (b,l,h).
// q pre-scaled by 0.125.  V written TRANSPOSED: (b,h,d,l).
// ============================================================
__global__ __launch_bounds__(256)
void norm_rope_split(const float* __restrict__ qkv, const float* __restrict__ rope,
                     const float* __restrict__ qw, const float* __restrict__ kw,
                     float* __restrict__ Q, float* __restrict__ K, float* __restrict__ Vt) {
    const int warp = (blockIdx.x * blockDim.x + threadIdx.x) >> 5;
    const int lane = threadIdx.x & 31;
    const int h  = warp & (HH - 1);
    const int bl = warp >> 4;               // b*L + l
    const int l  = bl & (LL - 1);
    const int b  = bl >> 11;

    const float* base = qkv + (size_t)bl * (3 * DD);
    const float c = rope[l * DH + lane * 2];
    const float s = rope[l * DH + lane * 2 + 1];
    const size_t obase = ((size_t)(b * HH + h) * LL + l) * DH;

    // ---- Q ----
    {
        float2 x = *(const float2*)(base + h * DH + lane * 2);
        float ss = x.x * x.x + x.y * x.y;
#pragma unroll
        for (int o = 16; o; o >>= 1) ss += __shfl_xor_sync(0xffffffffu, ss, o);
        float inv = rsqrtf(ss * (1.f / DH) + 1e-6f);
        float e = x.x * inv * qw[lane * 2];
        float o_ = x.y * inv * qw[lane * 2 + 1];
        Q[obase + lane * 2]     = 0.125f * (e * c - o_ * s);
        Q[obase + lane * 2 + 1] = 0.125f * (e * s + o_ * c);
    }
    // ---- K ----
    {
        float2 x = *(const float2*)(base + DD + h * DH + lane * 2);
        float ss = x.x * x.x + x.y * x.y;
#pragma unroll
        for (int o = 16; o; o >>= 1) ss += __shfl_xor_sync(0xffffffffu, ss, o);
        float inv = rsqrtf(ss * (1.f / DH) + 1e-6f);
        float e = x.x * inv * kw[lane * 2];
        float o_ = x.y * inv * kw[lane * 2 + 1];
        K[obase + lane * 2]     = e * c - o_ * s;
        K[obase + lane * 2 + 1] = e * s + o_ * c;
    }
    // ---- V transposed write: Vt[(b,h), d, l] ----
    {
        float2 v = *(const float2*)(base + 2 * DD + h * DH + lane * 2);
        const size_t vb = ((size_t)(b * HH + h) * DH + lane * 2) * LL + l;
        Vt[vb]      = v.x;
        Vt[vb + LL] = v.y;
    }
}

// ============================================================
// Flash attention, tf32 mma.sync (m16n8k8).
// Block = 128 thr (4 warps), 64 q-rows per block; warp owns 16.
// K tile staged in smem PERMUTED so B-frags load as LDS.64:
//   within each 8-col group, col u = h*4+c stored at position c*2+h.
// V staged from transposed global (b,h,d,l) with same j-permute.
// P round-trips C-frag -> smem (natural layout, aliases K) -> A-frag.
// ============================================================
#define ASTR 66   // smem row stride in floats (even, not mult of 4)

__global__ __launch_bounds__(128)
void attn_mma(const float* __restrict__ Qg, const float* __restrict__ Kg,
              const float* __restrict__ Vt, float* __restrict__ O) {
    __shared__ float KP[64 * ASTR];   // K tile, then aliased as P
    __shared__ float Vs[64 * ASTR];   // V^T tile: Vs[d][perm(j)]

    const int tid  = threadIdx.x;
    const int w    = tid >> 5;
    const int lane = tid & 31;
    const int g    = lane >> 2;       // group 0..7
    const int cg   = lane & 3;        // thread in group 0..3
    const int bh   = blockIdx.y;
    const int q0   = blockIdx.x * 64;

    // --- preload Q A-frags (scale already baked into Q) ---
    const float* qbase = Qg + ((size_t)bh * LL + q0) * DH;
    uint32_t qa[8][4];
    {
        const int r0 = w * 16 + g;
#pragma unroll
        for (int kt = 0; kt < 8; kt++) {
            qa[kt][0] = tf32bits(qbase[(size_t)r0 * DH + kt * 8 + cg]);
            qa[kt][1] = tf32bits(qbase[(size_t)(r0 + 8) * DH + kt * 8 + cg]);
            qa[kt][2] = tf32bits(qbase[(size_t)r0 * DH + kt * 8 + cg + 4]);
            qa[kt][3] = tf32bits(qbase[(size_t)(r0 + 8) * DH + kt * 8 + cg + 4]);
        }
    }

    float o[8][4];
#pragma unroll
    for (int dt = 0; dt < 8; dt++)
#pragma unroll
        for (int i = 0; i < 4; i++) o[dt][i] = 0.f;
    float m0 = -1e30f, m1 = -1e30f, l0 = 0.f, l1 = 0.f;

    for (int kvt = 0; kvt < LL / 64; kvt++) {
        __syncthreads();   // prior P/V reads complete before restaging

        // --- stage K (permuted cols, tf32) ---
        {
            const int j  = tid >> 1;
            const int db = (tid & 1) * 32;
            const float* kp = Kg + ((size_t)bh * LL + kvt * 64 + j) * DH + db;
            float* rowp = &KP[j * ASTR];
#pragma unroll
            for (int q = 0; q < 8; q++) {
                float4 v = *(const float4*)(kp + q * 4);
                int d0 = db + q * 4;
                float* dst = rowp + (d0 & ~7) + ((d0 >> 2) & 1);
                dst[0] = tf32f(v.x); dst[2] = tf32f(v.y);
                dst[4] = tf32f(v.z); dst[6] = tf32f(v.w);
            }
        }
        // --- stage V^T (permuted cols over j, tf32) ---
        {
            const int d  = tid >> 1;
            const int jb = (tid & 1) * 32;
            const float* vp = Vt + ((size_t)bh * DH + d) * LL + kvt * 64 + jb;
            float* rowp = &Vs[d * ASTR];
#pragma unroll
            for (int q = 0; q < 8; q++) {
                float4 v = *(const float4*)(vp + q * 4);
                int j0 = jb + q * 4;
                float* dst = rowp + (j0 & ~7) + ((j0 >> 2) & 1);
                dst[0] = tf32f(v.x); dst[2] = tf32f(v.y);
                dst[4] = tf32f(v.z); dst[6] = tf32f(v.w);
            }
        }
        __syncthreads();

        // --- QK^T: S frags (warp rows w*16+g, w*16+g+8) ---
        float s[8][4];
#pragma unroll
        for (int nt = 0; nt < 8; nt++)
#pragma unroll
            for (int i = 0; i < 4; i++) s[nt][i] = 0.f;
#pragma unroll
        for (int kt = 0; kt < 8; kt++) {
#pragma unroll
            for (int nt = 0; nt < 8; nt++) {
                uint2 b = *(const uint2*)&KP[(nt * 8 + g) * ASTR + kt * 8 + 2 * cg];
                mma_tf32(s[nt], qa[kt], b.x, b.y);
            }
        }
        __syncthreads();   // all warps done reading K before P overwrite

        // --- online softmax ---
        float mt0 = -1e30f, mt1 = -1e30f;
#pragma unroll
        for (int nt = 0; nt < 8; nt++) {
            mt0 = fmaxf(mt0, fmaxf(s[nt][0], s[nt][1]));
            mt1 = fmaxf(mt1, fmaxf(s[nt][2], s[nt][3]));
        }
        mt0 = fmaxf(mt0, __shfl_xor_sync(0xffffffffu, mt0, 1));
        mt0 = fmaxf(mt0, __shfl_xor_sync(0xffffffffu, mt0, 2));
        mt1 = fmaxf(mt1, __shfl_xor_sync(0xffffffffu, mt1, 1));
        mt1 = fmaxf(mt1, __shfl_xor_sync(0xffffffffu, mt1, 2));

        const float mn0 = fmaxf(m0, mt0);
        const float mn1 = fmaxf(m1, mt1);
        const float a0 = __expf(m0 - mn0);
        const float a1 = __expf(m1 - mn1);
        l0 *= a0; l1 *= a1;
#pragma unroll
        for (int dt = 0; dt < 8; dt++) {
            o[dt][0] *= a0; o[dt][1] *= a0;
            o[dt][2] *= a1; o[dt][3] *= a1;
        }

        const int r0 = w * 16 + g;
        float ps0 = 0.f, ps1 = 0.f;
#pragma unroll
        for (int nt = 0; nt < 8; nt++) {
            float p00 = __expf(s[nt][0] - mn0);
            float p01 = __expf(s[nt][1] - mn0);
            float p10 = __expf(s[nt][2] - mn1);
            float p11 = __expf(s[nt][3] - mn1);
            ps0 += p00 + p01;
            ps1 += p10 + p11;
            float2 w0 = make_float2(tf32f(p00), tf32f(p01));
            float2 w1 = make_float2(tf32f(p10), tf32f(p11));
            *(float2*)&KP[r0 * ASTR + nt * 8 + 2 * cg] = w0;
            *(float2*)&KP[(r0 + 8) * ASTR + nt * 8 + 2 * cg] = w1;
        }
        ps0 += __shfl_xor_sync(0xffffffffu, ps0, 1);
        ps0 += __shfl_xor_sync(0xffffffffu, ps0, 2);
        ps1 += __shfl_xor_sync(0xffffffffu, ps1, 1);
        ps1 += __shfl_xor_sync(0xffffffffu, ps1, 2);
        l0 += ps0; l1 += ps1;
        m0 = mn0; m1 = mn1;
        __syncwarp();

        // --- P @ V ---
#pragma unroll
        for (int kt = 0; kt < 8; kt++) {
            uint32_t pa[4];
            pa[0] = __float_as_uint(KP[r0 * ASTR + kt * 8 + cg]);
            pa[1] = __float_as_uint(KP[(r0 + 8) * ASTR + kt * 8 + cg]);
            pa[2] = __float_as_uint(KP[r0 * ASTR + kt * 8 + cg + 4]);
            pa[3] = __float_as_uint(KP[(r0 + 8) * ASTR + kt * 8 + cg + 4]);
#pragma unroll
            for (int dt = 0; dt < 8; dt++) {
                uint2 b = *(const uint2*)&Vs[(dt * 8 + g) * ASTR + kt * 8 + 2 * cg];
                mma_tf32(o[dt], pa, b.x, b.y);
            }
        }
    }

    // --- epilogue: divide by l, store to (b, l, h*64+d) ---
    const float il0 = 1.f / l0;
    const float il1 = 1.f / l1;
    const int b = bh >> 4, h = bh & (HH - 1);
    const int lq0 = q0 + w * 16 + g;
    float* ob0 = O + ((size_t)(b * LL + lq0)) * DD + h * DH;
    float* ob1 = O + ((size_t)(b * LL + lq0 + 8)) * DD + h * DH;
#pragma unroll
    for (int dt = 0; dt < 8; dt++) {
        float2 v0 = make_float2(o[dt][0] * il0, o[dt][1] * il0);
        float2 v1 = make_float2(o[dt][2] * il1, o[dt][3] * il1);
        *(float2*)(ob0 + dt * 8 + 2 * cg) = v0;
        *(float2*)(ob1 + dt * 8 + 2 * cg) = v1;
    }
}

// ============================================================
extern "C" void kernel_launch(void* const* d_in, const int* in_sizes, int n_in,
                              void* d_out, int out_size) {
    const float* x      = (const float*)d_in[0];
    const float* rope   = (const float*)d_in[1];
    const float* w_qkv  = (const float*)d_in[2];
    const float* w_proj = (const float*)d_in[3];
    const float* qw     = (const float*)d_in[4];
    const float* kw     = (const float*)d_in[5];
    float* out = (float*)d_out;

    float *qkv, *Q, *K, *V, *O;
    cudaGetSymbolAddress((void**)&qkv, g_qkv);
    cudaGetSymbolAddress((void**)&Q, g_q);
    cudaGetSymbolAddress((void**)&K, g_k);
    cudaGetSymbolAddress((void**)&V, g_v);
    cudaGetSymbolAddress((void**)&O, g_o);

    // 1) qkv = x @ w_qkv^T
    sgemm_nt_f2<<<dim3(3 * DD / GBN, MTOT / GBM), 256>>>(x, w_qkv, qkv, MTOT, 3 * DD, DD);

    // 2) rmsnorm + rope + head split (q pre-scaled; V transposed)
    norm_rope_split<<<(MTOT * HH) / 8, 256>>>(qkv, rope, qw, kw, Q, K, V);

    // 3) attention (tf32 mma) -> g_o in (b,l,h*64+d) layout
    attn_mma<<<dim3(LL / 64, BB * HH), 128>>>(Q, K, V, O);

    // 4) out = O @ w_proj^T
    sgemm_nt_f2<<<dim3(DD / GBN, MTOT / GBM), 256>>>(O, w_proj, out, MTOT, DD, DD);
}

// round 6
// speedup vs baseline: 1.6392x; 1.0493x over previous
#include <cuda_runtime.h>
#include <cstdint>

// Problem dims (fixed by the reference)
#define BB 2
#define LL 2048
#define DD 1024
#define HH 16
#define DH 64
#define MTOT (BB*LL)        // 4096

typedef unsigned long long ull;

// ---------------- f32x2 packed helpers (sm_103a) ----------------
__device__ __forceinline__ ull pk2(float lo, float hi) {
    ull r; asm("mov.b64 %0, {%1, %2};" : "=l"(r) : "f"(lo), "f"(hi)); return r;
}
__device__ __forceinline__ void upk2(ull v, float& lo, float& hi) {
    asm("mov.b64 {%0, %1}, %2;" : "=f"(lo), "=f"(hi) : "l"(v));
}
__device__ __forceinline__ ull fma2(ull a, ull b, ull c) {
    ull r; asm("fma.rn.f32x2 %0, %1, %2, %3;" : "=l"(r) : "l"(a), "l"(b), "l"(c)); return r;
}

// ---------------- tf32 mma helpers (sm_80+ base target) ----------------
__device__ __forceinline__ uint32_t tf32bits(float f) {
    uint32_t r; asm("cvt.rna.tf32.f32 %0, %1;" : "=r"(r) : "f"(f)); return r;
}
__device__ __forceinline__ float tf32f(float f) {
    return __uint_as_float(tf32bits(f));
}
__device__ __forceinline__ void mma_tf32(float c[4], const uint32_t a[4],
                                         uint32_t b0, uint32_t b1) {
    asm volatile(
        "mma.sync.aligned.m16n8k8.row.col.f32.tf32.tf32.f32 "
        "{%0,%1,%2,%3}, {%4,%5,%6,%7}, {%8,%9}, {%0,%1,%2,%3};"
        : "+f"(c[0]), "+f"(c[1]), "+f"(c[2]), "+f"(c[3])
        : "r"(a[0]), "r"(a[1]), "r"(a[2]), "r"(a[3]), "r"(b0), "r"(b1));
}

// -------- scratch (static device globals; no allocation allowed) --------
__device__ float g_qkv[(size_t)MTOT * 3 * DD];          // (B*L, 3072)
__device__ float g_q[(size_t)BB * HH * LL * DH];        // (b,h,l,d)
__device__ float g_k[(size_t)BB * HH * LL * DH];
__device__ float g_v[(size_t)BB * HH * LL * DH];        // TRANSPOSED: (b,h,d,l)
__device__ float g_o[(size_t)MTOT * DD];                // (b,l, h*64+d)

// ============================================================
// SGEMM: C[M][N] = A[M][K] * B[N][K]^T  (both K-major), f32x2.
// (proven round-2 kernel, unchanged)
// ============================================================
#define GBM 128
#define GBN 128
#define GBK 16
#define GPAD 4

__global__ __launch_bounds__(256)
void sgemm_nt_f2(const float* __restrict__ A, const float* __restrict__ B,
                 float* __restrict__ C, int M, int N, int K) {
    __shared__ float As[GBK][GBM + GPAD];
    __shared__ float Bs[GBK][GBN + GPAD];

    const int tid = threadIdx.x;
    const int tx = tid & 15;
    const int ty = tid >> 4;
    const int lr = tid >> 1;
    const int lk = (tid & 1) * 8;
    const int m0 = blockIdx.y * GBM;
    const int n0 = blockIdx.x * GBN;

    ull acc[2][4][2][2];
#pragma unroll
    for (int rb = 0; rb < 2; rb++)
#pragma unroll
        for (int i = 0; i < 4; i++)
#pragma unroll
            for (int cb = 0; cb < 2; cb++) {
                acc[rb][i][cb][0] = 0ull; acc[rb][i][cb][1] = 0ull;
            }

    const float* aptr = A + (size_t)(m0 + lr) * K + lk;
    const float* bptr = B + (size_t)(n0 + lr) * K + lk;

    float4 pa0 = *(const float4*)(aptr);
    float4 pa1 = *(const float4*)(aptr + 4);
    float4 pb0 = *(const float4*)(bptr);
    float4 pb1 = *(const float4*)(bptr + 4);

    for (int k0 = 0; k0 < K; k0 += GBK) {
        As[lk + 0][lr] = pa0.x; As[lk + 1][lr] = pa0.y;
        As[lk + 2][lr] = pa0.z; As[lk + 3][lr] = pa0.w;
        As[lk + 4][lr] = pa1.x; As[lk + 5][lr] = pa1.y;
        As[lk + 6][lr] = pa1.z; As[lk + 7][lr] = pa1.w;
        Bs[lk + 0][lr] = pb0.x; Bs[lk + 1][lr] = pb0.y;
        Bs[lk + 2][lr] = pb0.z; Bs[lk + 3][lr] = pb0.w;
        Bs[lk + 4][lr] = pb1.x; Bs[lk + 5][lr] = pb1.y;
        Bs[lk + 6][lr] = pb1.z; Bs[lk + 7][lr] = pb1.w;
        __syncthreads();

        if (k0 + GBK < K) {
            const float* ap = aptr + k0 + GBK;
            const float* bp = bptr + k0 + GBK;
            pa0 = *(const float4*)(ap);
            pa1 = *(const float4*)(ap + 4);
            pb0 = *(const float4*)(bp);
            pb1 = *(const float4*)(bp + 4);
        }

#pragma unroll
        for (int k = 0; k < GBK; k++) {
            float4 a0v = *(const float4*)&As[k][ty * 4];
            float4 a1v = *(const float4*)&As[k][64 + ty * 4];
            ulonglong2 b0v = *(const ulonglong2*)&Bs[k][tx * 4];
            ulonglong2 b1v = *(const ulonglong2*)&Bs[k][64 + tx * 4];
            ull bp_[2][2] = {{b0v.x, b0v.y}, {b1v.x, b1v.y}};
            float am[2][4] = {{a0v.x, a0v.y, a0v.z, a0v.w},
                              {a1v.x, a1v.y, a1v.z, a1v.w}};
#pragma unroll
            for (int rb = 0; rb < 2; rb++)
#pragma unroll
                for (int i = 0; i < 4; i++) {
                    ull ai = pk2(am[rb][i], am[rb][i]);
#pragma unroll
                    for (int cb = 0; cb < 2; cb++) {
                        acc[rb][i][cb][0] = fma2(ai, bp_[cb][0], acc[rb][i][cb][0]);
                        acc[rb][i][cb][1] = fma2(ai, bp_[cb][1], acc[rb][i][cb][1]);
                    }
                }
        }
        __syncthreads();
    }

#pragma unroll
    for (int rb = 0; rb < 2; rb++)
#pragma unroll
        for (int i = 0; i < 4; i++) {
            int row = m0 + rb * 64 + ty * 4 + i;
#pragma unroll
            for (int cb = 0; cb < 2; cb++) {
                float4 o;
                upk2(acc[rb][i][cb][0], o.x, o.y);
                upk2(acc[rb][i][cb][1], o.z, o.w);
                *(float4*)&C[(size_t)row * N + n0 + cb * 64 + tx * 4] = o;
            }
        }
}

// ============================================================
// rmsnorm + RoPE + head split.  One warp per (b,l,h).
// q pre-scaled by 0.125.  V written TRANSPOSED: (b,h,d,l).
// ============================================================
__global__ __launch_bounds__(256)
void norm_rope_split(const float* __restrict__ qkv, const float* __restrict__ rope,
                     const float* __restrict__ qw, const float* __restrict__ kw,
                     float* __restrict__ Q, float* __restrict__ K, float* __restrict__ Vt) {
    const int warp = (blockIdx.x * blockDim.x + threadIdx.x) >> 5;
    const int lane = threadIdx.x & 31;
    const int h  = warp & (HH - 1);
    const int bl = warp >> 4;               // b*L + l
    const int l  = bl & (LL - 1);
    const int b  = bl >> 11;

    const float* base = qkv + (size_t)bl * (3 * DD);
    const float c = rope[l * DH + lane * 2];
    const float s = rope[l * DH + lane * 2 + 1];
    const size_t obase = ((size_t)(b * HH + h) * LL + l) * DH;

    // ---- Q ----
    {
        float2 x = *(const float2*)(base + h * DH + lane * 2);
        float ss = x.x * x.x + x.y * x.y;
#pragma unroll
        for (int o = 16; o; o >>= 1) ss += __shfl_xor_sync(0xffffffffu, ss, o);
        float inv = rsqrtf(ss * (1.f / DH) + 1e-6f);
        float e = x.x * inv * qw[lane * 2];
        float o_ = x.y * inv * qw[lane * 2 + 1];
        Q[obase + lane * 2]     = 0.125f * (e * c - o_ * s);
        Q[obase + lane * 2 + 1] = 0.125f * (e * s + o_ * c);
    }
    // ---- K ----
    {
        float2 x = *(const float2*)(base + DD + h * DH + lane * 2);
        float ss = x.x * x.x + x.y * x.y;
#pragma unroll
        for (int o = 16; o; o >>= 1) ss += __shfl_xor_sync(0xffffffffu, ss, o);
        float inv = rsqrtf(ss * (1.f / DH) + 1e-6f);
        float e = x.x * inv * kw[lane * 2];
        float o_ = x.y * inv * kw[lane * 2 + 1];
        K[obase + lane * 2]     = e * c - o_ * s;
        K[obase + lane * 2 + 1] = e * s + o_ * c;
    }
    // ---- V transposed write: Vt[(b,h), d, l] ----
    {
        float2 v = *(const float2*)(base + 2 * DD + h * DH + lane * 2);
        const size_t vb = ((size_t)(b * HH + h) * DH + lane * 2) * LL + l;
        Vt[vb]      = v.x;
        Vt[vb + LL] = v.y;
    }
}

// ============================================================
// Flash attention, tf32 mma.sync (m16n8k8).
// Block = 256 thr (8 warps), 128 q-rows per block; warp owns 16.
// kv tile = 64.  K/V staged permuted for LDS.64 B-frags.
// P in a SEPARATE warp-exclusive smem region (only __syncwarp).
// K/V global loads prefetched into regs before the reads-done
// barrier so global latency overlaps the barrier wait.
// ============================================================
#define ASTR 66   // smem row stride in floats (even, not mult of 4)
#define KS_OFF 0
#define VS_OFF (64 * ASTR)
#define PS_OFF (128 * ASTR)
#define ATT_SMEM ((128 * ASTR + 128 * ASTR) * 4)   // 67584 B

__global__ __launch_bounds__(256)
void attn_mma(const float* __restrict__ Qg, const float* __restrict__ Kg,
              const float* __restrict__ Vt, float* __restrict__ O) {
    extern __shared__ float sm[];
    float* Ks = sm + KS_OFF;
    float* Vs = sm + VS_OFF;
    float* Ps = sm + PS_OFF;

    const int tid  = threadIdx.x;
    const int w    = tid >> 5;
    const int lane = tid & 31;
    const int g    = lane >> 2;       // group 0..7
    const int cg   = lane & 3;        // thread in group 0..3
    const int bh   = blockIdx.y;
    const int q0   = blockIdx.x * 128;
    const int r0   = w * 16 + g;      // this thread's base q-row in block

    // --- staging geometry (256 threads cover a 64x64 tile; 16 floats each) ---
    const int sr = tid >> 2;               // row 0..63 (K: j, V: d)
    const int sc = (tid & 3) * 16;         // col base 0/16/32/48
    const float* kbase = Kg + ((size_t)bh * LL + sr) * DH + sc;
    const float* vbase = Vt + ((size_t)bh * DH + sr) * LL + sc;
    float* krow = &Ks[sr * ASTR];
    float* vrow = &Vs[sr * ASTR];

    // --- preload Q A-frags (scale already baked into Q) ---
    const float* qbase = Qg + ((size_t)bh * LL + q0) * DH;
    uint32_t qa[8][4];
#pragma unroll
    for (int kt = 0; kt < 8; kt++) {
        qa[kt][0] = tf32bits(qbase[(size_t)r0 * DH + kt * 8 + cg]);
        qa[kt][1] = tf32bits(qbase[(size_t)(r0 + 8) * DH + kt * 8 + cg]);
        qa[kt][2] = tf32bits(qbase[(size_t)r0 * DH + kt * 8 + cg + 4]);
        qa[kt][3] = tf32bits(qbase[(size_t)(r0 + 8) * DH + kt * 8 + cg + 4]);
    }

    float o[8][4];
#pragma unroll
    for (int dt = 0; dt < 8; dt++)
#pragma unroll
        for (int i = 0; i < 4; i++) o[dt][i] = 0.f;
    float m0 = -1e30f, m1 = -1e30f, l0 = 0.f, l1 = 0.f;

    for (int kvt = 0; kvt < LL / 64; kvt++) {
        // --- prefetch this tile's K/V rows into registers (no barrier dep) ---
        float4 kr[4], vr[4];
#pragma unroll
        for (int q = 0; q < 4; q++) {
            kr[q] = *(const float4*)(kbase + (size_t)kvt * 64 * DH + q * 4);
            vr[q] = *(const float4*)(vbase + kvt * 64 + q * 4);
        }
        __syncthreads();   // all warps done reading Ks/Vs of previous tile

        // --- store (tf32-converted, pair-permuted) ---
#pragma unroll
        for (int q = 0; q < 4; q++) {
            int d0 = sc + q * 4;
            float* kd = krow + (d0 & ~7) + ((d0 >> 2) & 1);
            kd[0] = tf32f(kr[q].x); kd[2] = tf32f(kr[q].y);
            kd[4] = tf32f(kr[q].z); kd[6] = tf32f(kr[q].w);
            float* vd = vrow + (d0 & ~7) + ((d0 >> 2) & 1);
            vd[0] = tf32f(vr[q].x); vd[2] = tf32f(vr[q].y);
            vd[4] = tf32f(vr[q].z); vd[6] = tf32f(vr[q].w);
        }
        __syncthreads();

        // --- QK^T: S frags (rows r0, r0+8) ---
        float s[8][4];
#pragma unroll
        for (int nt = 0; nt < 8; nt++)
#pragma unroll
            for (int i = 0; i < 4; i++) s[nt][i] = 0.f;
#pragma unroll
        for (int kt = 0; kt < 8; kt++) {
#pragma unroll
            for (int nt = 0; nt < 8; nt++) {
                uint2 b = *(const uint2*)&Ks[(nt * 8 + g) * ASTR + kt * 8 + 2 * cg];
                mma_tf32(s[nt], qa[kt], b.x, b.y);
            }
        }

        // --- online softmax ---
        float mt0 = -1e30f, mt1 = -1e30f;
#pragma unroll
        for (int nt = 0; nt < 8; nt++) {
            mt0 = fmaxf(mt0, fmaxf(s[nt][0], s[nt][1]));
            mt1 = fmaxf(mt1, fmaxf(s[nt][2], s[nt][3]));
        }
        mt0 = fmaxf(mt0, __shfl_xor_sync(0xffffffffu, mt0, 1));
        mt0 = fmaxf(mt0, __shfl_xor_sync(0xffffffffu, mt0, 2));
        mt1 = fmaxf(mt1, __shfl_xor_sync(0xffffffffu, mt1, 1));
        mt1 = fmaxf(mt1, __shfl_xor_sync(0xffffffffu, mt1, 2));

        const float mn0 = fmaxf(m0, mt0);
        const float mn1 = fmaxf(m1, mt1);
        const float a0 = __expf(m0 - mn0);
        const float a1 = __expf(m1 - mn1);
        l0 *= a0; l1 *= a1;
#pragma unroll
        for (int dt = 0; dt < 8; dt++) {
            o[dt][0] *= a0; o[dt][1] *= a0;
            o[dt][2] *= a1; o[dt][3] *= a1;
        }

        float ps0 = 0.f, ps1 = 0.f;
#pragma unroll
        for (int nt = 0; nt < 8; nt++) {
            float p00 = __expf(s[nt][0] - mn0);
            float p01 = __expf(s[nt][1] - mn0);
            float p10 = __expf(s[nt][2] - mn1);
            float p11 = __expf(s[nt][3] - mn1);
            ps0 += p00 + p01;
            ps1 += p10 + p11;
            float2 w0 = make_float2(tf32f(p00), tf32f(p01));
            float2 w1 = make_float2(tf32f(p10), tf32f(p11));
            *(float2*)&Ps[r0 * ASTR + nt * 8 + 2 * cg] = w0;
            *(float2*)&Ps[(r0 + 8) * ASTR + nt * 8 + 2 * cg] = w1;
        }
        ps0 += __shfl_xor_sync(0xffffffffu, ps0, 1);
        ps0 += __shfl_xor_sync(0xffffffffu, ps0, 2);
        ps1 += __shfl_xor_sync(0xffffffffu, ps1, 1);
        ps1 += __shfl_xor_sync(0xffffffffu, ps1, 2);
        l0 += ps0; l1 += ps1;
        m0 = mn0; m1 = mn1;
        __syncwarp();      // P rows are warp-exclusive

        // --- P @ V ---
#pragma unroll
        for (int kt = 0; kt < 8; kt++) {
            uint32_t pa[4];
            pa[0] = __float_as_uint(Ps[r0 * ASTR + kt * 8 + cg]);
            pa[1] = __float_as_uint(Ps[(r0 + 8) * ASTR + kt * 8 + cg]);
            pa[2] = __float_as_uint(Ps[r0 * ASTR + kt * 8 + cg + 4]);
            pa[3] = __float_as_uint(Ps[(r0 + 8) * ASTR + kt * 8 + cg + 4]);
#pragma unroll
            for (int dt = 0; dt < 8; dt++) {
                uint2 b = *(const uint2*)&Vs[(dt * 8 + g) * ASTR + kt * 8 + 2 * cg];
                mma_tf32(o[dt], pa, b.x, b.y);
            }
        }
    }

    // --- epilogue: divide by l, store to (b, l, h*64+d) ---
    const float il0 = 1.f / l0;
    const float il1 = 1.f / l1;
    const int b = bh >> 4, h = bh & (HH - 1);
    const int lq0 = q0 + r0;
    float* ob0 = O + ((size_t)(b * LL + lq0)) * DD + h * DH;
    float* ob1 = O + ((size_t)(b * LL + lq0 + 8)) * DD + h * DH;
#pragma unroll
    for (int dt = 0; dt < 8; dt++) {
        float2 v0 = make_float2(o[dt][0] * il0, o[dt][1] * il0);
        float2 v1 = make_float2(o[dt][2] * il1, o[dt][3] * il1);
        *(float2*)(ob0 + dt * 8 + 2 * cg) = v0;
        *(float2*)(ob1 + dt * 8 + 2 * cg) = v1;
    }
}

// ============================================================
extern "C" void kernel_launch(void* const* d_in, const int* in_sizes, int n_in,
                              void* d_out, int out_size) {
    const float* x      = (const float*)d_in[0];
    const float* rope   = (const float*)d_in[1];
    const float* w_qkv  = (const float*)d_in[2];
    const float* w_proj = (const float*)d_in[3];
    const float* qw     = (const float*)d_in[4];
    const float* kw     = (const float*)d_in[5];
    float* out = (float*)d_out;

    float *qkv, *Q, *K, *V, *O;
    cudaGetSymbolAddress((void**)&qkv, g_qkv);
    cudaGetSymbolAddress((void**)&Q, g_q);
    cudaGetSymbolAddress((void**)&K, g_k);
    cudaGetSymbolAddress((void**)&V, g_v);
    cudaGetSymbolAddress((void**)&O, g_o);

    cudaFuncSetAttribute(attn_mma, cudaFuncAttributeMaxDynamicSharedMemorySize, ATT_SMEM);

    // 1) qkv = x @ w_qkv^T
    sgemm_nt_f2<<<dim3(3 * DD / GBN, MTOT / GBM), 256>>>(x, w_qkv, qkv, MTOT, 3 * DD, DD);

    // 2) rmsnorm + rope + head split (q pre-scaled; V transposed)
    norm_rope_split<<<(MTOT * HH) / 8, 256>>>(qkv, rope, qw, kw, Q, K, V);

    // 3) attention (tf32 mma, 128 q-rows/block) -> g_o
    attn_mma<<<dim3(LL / 128, BB * HH), 256, ATT_SMEM>>>(Q, K, V, O);

    // 4) out = O @ w_proj^T
    sgemm_nt_f2<<<dim3(DD / GBN, MTOT / GBM), 256>>>(O, w_proj, out, MTOT, DD, DD);
}

// round 8
// speedup vs baseline: 1.9867x; 1.2120x over previous
#include <cuda_runtime.h>
#include <cstdint>

// Problem dims (fixed by the reference)
#define BB 2
#define LL 2048
#define DD 1024
#define HH 16
#define DH 64
#define MTOT (BB*LL)        // 4096

typedef unsigned long long ull;

// ---------------- f32x2 packed helpers (sm_103a) ----------------
__device__ __forceinline__ ull pk2(float lo, float hi) {
    ull r; asm("mov.b64 %0, {%1, %2};" : "=l"(r) : "f"(lo), "f"(hi)); return r;
}
__device__ __forceinline__ void upk2(ull v, float& lo, float& hi) {
    asm("mov.b64 {%0, %1}, %2;" : "=f"(lo), "=f"(hi) : "l"(v));
}
__device__ __forceinline__ ull fma2(ull a, ull b, ull c) {
    ull r; asm("fma.rn.f32x2 %0, %1, %2, %3;" : "=l"(r) : "l"(a), "l"(b), "l"(c)); return r;
}

// ---------------- tf32 mma helpers (sm_80+ base target) ----------------
__device__ __forceinline__ uint32_t tf32bits(float f) {
    uint32_t r; asm("cvt.rna.tf32.f32 %0, %1;" : "=r"(r) : "f"(f)); return r;
}
__device__ __forceinline__ float tf32f(float f) {
    return __uint_as_float(tf32bits(f));
}
__device__ __forceinline__ void mma_tf32(float c[4], const uint32_t a[4],
                                         uint32_t b0, uint32_t b1) {
    asm volatile(
        "mma.sync.aligned.m16n8k8.row.col.f32.tf32.tf32.f32 "
        "{%0,%1,%2,%3}, {%4,%5,%6,%7}, {%8,%9}, {%0,%1,%2,%3};"
        : "+f"(c[0]), "+f"(c[1]), "+f"(c[2]), "+f"(c[3])
        : "r"(a[0]), "r"(a[1]), "r"(a[2]), "r"(a[3]), "r"(b0), "r"(b1));
}

// -------- scratch (static device globals; no allocation allowed) --------
__device__ float g_qkv[(size_t)MTOT * 3 * DD];          // (B*L, 3072)
__device__ float g_q[(size_t)BB * HH * LL * DH];        // (b,h,l,d)
__device__ float g_k[(size_t)BB * HH * LL * DH];
__device__ float g_v[(size_t)BB * HH * LL * DH];        // TRANSPOSED: (b,h,d,l)
__device__ float g_o[(size_t)MTOT * DD];                // (b,l, h*64+d)

// ============================================================
// SGEMM: C[M][N] = A[M][K] * B[N][K]^T  (both K-major), f32x2.
// (proven round-2 kernel, unchanged)
// ============================================================
#define GBM 128
#define GBN 128
#define GBK 16
#define GPAD 4

__global__ __launch_bounds__(256)
void sgemm_nt_f2(const float* __restrict__ A, const float* __restrict__ B,
                 float* __restrict__ C, int M, int N, int K) {
    __shared__ float As[GBK][GBM + GPAD];
    __shared__ float Bs[GBK][GBN + GPAD];

    const int tid = threadIdx.x;
    const int tx = tid & 15;
    const int ty = tid >> 4;
    const int lr = tid >> 1;
    const int lk = (tid & 1) * 8;
    const int m0 = blockIdx.y * GBM;
    const int n0 = blockIdx.x * GBN;

    ull acc[2][4][2][2];
#pragma unroll
    for (int rb = 0; rb < 2; rb++)
#pragma unroll
        for (int i = 0; i < 4; i++)
#pragma unroll
            for (int cb = 0; cb < 2; cb++) {
                acc[rb][i][cb][0] = 0ull; acc[rb][i][cb][1] = 0ull;
            }

    const float* aptr = A + (size_t)(m0 + lr) * K + lk;
    const float* bptr = B + (size_t)(n0 + lr) * K + lk;

    float4 pa0 = *(const float4*)(aptr);
    float4 pa1 = *(const float4*)(aptr + 4);
    float4 pb0 = *(const float4*)(bptr);
    float4 pb1 = *(const float4*)(bptr + 4);

    for (int k0 = 0; k0 < K; k0 += GBK) {
        As[lk + 0][lr] = pa0.x; As[lk + 1][lr] = pa0.y;
        As[lk + 2][lr] = pa0.z; As[lk + 3][lr] = pa0.w;
        As[lk + 4][lr] = pa1.x; As[lk + 5][lr] = pa1.y;
        As[lk + 6][lr] = pa1.z; As[lk + 7][lr] = pa1.w;
        Bs[lk + 0][lr] = pb0.x; Bs[lk + 1][lr] = pb0.y;
        Bs[lk + 2][lr] = pb0.z; Bs[lk + 3][lr] = pb0.w;
        Bs[lk + 4][lr] = pb1.x; Bs[lk + 5][lr] = pb1.y;
        Bs[lk + 6][lr] = pb1.z; Bs[lk + 7][lr] = pb1.w;
        __syncthreads();

        if (k0 + GBK < K) {
            const float* ap = aptr + k0 + GBK;
            const float* bp = bptr + k0 + GBK;
            pa0 = *(const float4*)(ap);
            pa1 = *(const float4*)(ap + 4);
            pb0 = *(const float4*)(bp);
            pb1 = *(const float4*)(bp + 4);
        }

#pragma unroll
        for (int k = 0; k < GBK; k++) {
            float4 a0v = *(const float4*)&As[k][ty * 4];
            float4 a1v = *(const float4*)&As[k][64 + ty * 4];
            ulonglong2 b0v = *(const ulonglong2*)&Bs[k][tx * 4];
            ulonglong2 b1v = *(const ulonglong2*)&Bs[k][64 + tx * 4];
            ull bp_[2][2] = {{b0v.x, b0v.y}, {b1v.x, b1v.y}};
            float am[2][4] = {{a0v.x, a0v.y, a0v.z, a0v.w},
                              {a1v.x, a1v.y, a1v.z, a1v.w}};
#pragma unroll
            for (int rb = 0; rb < 2; rb++)
#pragma unroll
                for (int i = 0; i < 4; i++) {
                    ull ai = pk2(am[rb][i], am[rb][i]);
#pragma unroll
                    for (int cb = 0; cb < 2; cb++) {
                        acc[rb][i][cb][0] = fma2(ai, bp_[cb][0], acc[rb][i][cb][0]);
                        acc[rb][i][cb][1] = fma2(ai, bp_[cb][1], acc[rb][i][cb][1]);
                    }
                }
        }
        __syncthreads();
    }

#pragma unroll
    for (int rb = 0; rb < 2; rb++)
#pragma unroll
        for (int i = 0; i < 4; i++) {
            int row = m0 + rb * 64 + ty * 4 + i;
#pragma unroll
            for (int cb = 0; cb < 2; cb++) {
                float4 o;
                upk2(acc[rb][i][cb][0], o.x, o.y);
                upk2(acc[rb][i][cb][1], o.z, o.w);
                *(float4*)&C[(size_t)row * N + n0 + cb * 64 + tx * 4] = o;
            }
        }
}

// ============================================================
// rmsnorm + RoPE + head split.  One warp per (b,l,h).
// q pre-scaled by 0.125.  V written TRANSPOSED: (b,h,d,l).
// ============================================================
__global__ __launch_bounds__(256)
void norm_rope_split(const float* __restrict__ qkv, const float* __restrict__ rope,
                     const float* __restrict__ qw, const float* __restrict__ kw,
                     float* __restrict__ Q, float* __restrict__ K, float* __restrict__ Vt) {
    const int warp = (blockIdx.x * blockDim.x + threadIdx.x) >> 5;
    const int lane = threadIdx.x & 31;
    const int h  = warp & (HH - 1);
    const int bl = warp >> 4;               // b*L + l
    const int l  = bl & (LL - 1);
    const int b  = bl >> 11;

    const float* base = qkv + (size_t)bl * (3 * DD);
    const float c = rope[l * DH + lane * 2];
    const float s = rope[l * DH + lane * 2 + 1];
    const size_t obase = ((size_t)(b * HH + h) * LL + l) * DH;

    // ---- Q ----
    {
        float2 x = *(const float2*)(base + h * DH + lane * 2);
        float ss = x.x * x.x + x.y * x.y;
#pragma unroll
        for (int o = 16; o; o >>= 1) ss += __shfl_xor_sync(0xffffffffu, ss, o);
        float inv = rsqrtf(ss * (1.f / DH) + 1e-6f);
        float e = x.x * inv * qw[lane * 2];
        float o_ = x.y * inv * qw[lane * 2 + 1];
        Q[obase + lane * 2]     = 0.125f * (e * c - o_ * s);
        Q[obase + lane * 2 + 1] = 0.125f * (e * s + o_ * c);
    }
    // ---- K ----
    {
        float2 x = *(const float2*)(base + DD + h * DH + lane * 2);
        float ss = x.x * x.x + x.y * x.y;
#pragma unroll
        for (int o = 16; o; o >>= 1) ss += __shfl_xor_sync(0xffffffffu, ss, o);
        float inv = rsqrtf(ss * (1.f / DH) + 1e-6f);
        float e = x.x * inv * kw[lane * 2];
        float o_ = x.y * inv * kw[lane * 2 + 1];
        K[obase + lane * 2]     = e * c - o_ * s;
        K[obase + lane * 2 + 1] = e * s + o_ * c;
    }
    // ---- V transposed write: Vt[(b,h), d, l] ----
    {
        float2 v = *(const float2*)(base + 2 * DD + h * DH + lane * 2);
        const size_t vb = ((size_t)(b * HH + h) * DH + lane * 2) * LL + l;
        Vt[vb]      = v.x;
        Vt[vb + LL] = v.y;
    }
}

// ============================================================
// Flash attention, tf32 mma.sync (m16n8k8), P kept in registers.
// Block = 256 thr (8 warps), 128 q-rows; kv tile = 64.
// Ks: pair-permuted cols (B-frag LDS.64 -> cols {cg, cg+4}).
// Vs: STRAIGHT cols (B-frag LDS.64 -> cols {2cg, 2cg+1}) so the
//   S C-frag (cols 2cg,2cg+1) feeds PV A-frags directly — the
//   j-permutation cancels between P and V.
// Double-buffered K/V smem -> ONE __syncthreads per kv tile;
// global prefetch issued before the barrier.
// ============================================================
#define KSTR 66   // Ks row stride (floats)
#define VSTR 68   // Vs row stride (floats), 16B-aligned rows
#define KBUF (64 * KSTR)
#define VBUF (64 * VSTR)
#define KS_OFF 0
#define VS_OFF (2 * KBUF)
#define ATT_SMEM ((2 * KBUF + 2 * VBUF) * 4)   // 68608 B

__global__ __launch_bounds__(256)
void attn_mma(const float* __restrict__ Qg, const float* __restrict__ Kg,
              const float* __restrict__ Vt, float* __restrict__ O) {
    extern __shared__ float sm[];

    const int tid  = threadIdx.x;
    const int w    = tid >> 5;
    const int lane = tid & 31;
    const int g    = lane >> 2;       // group 0..7
    const int cg   = lane & 3;        // thread in group 0..3
    const int bh   = blockIdx.y;
    const int q0   = blockIdx.x * 128;
    const int r0   = w * 16 + g;      // this thread's base q-row in block

    // --- staging geometry (256 threads cover a 64x64 tile; 16 floats each) ---
    const int sr = tid >> 2;               // row 0..63 (K: j, V: d)
    const int sc = (tid & 3) * 16;         // col base 0/16/32/48
    const float* kbase = Kg + ((size_t)bh * LL + sr) * DH + sc;
    const float* vbase = Vt + ((size_t)bh * DH + sr) * LL + sc;

    // --- preload Q A-frags (scale already baked into Q) ---
    const float* qbase = Qg + ((size_t)bh * LL + q0) * DH;
    uint32_t qa[8][4];
#pragma unroll
    for (int kt = 0; kt < 8; kt++) {
        qa[kt][0] = tf32bits(qbase[(size_t)r0 * DH + kt * 8 + cg]);
        qa[kt][1] = tf32bits(qbase[(size_t)(r0 + 8) * DH + kt * 8 + cg]);
        qa[kt][2] = tf32bits(qbase[(size_t)r0 * DH + kt * 8 + cg + 4]);
        qa[kt][3] = tf32bits(qbase[(size_t)(r0 + 8) * DH + kt * 8 + cg + 4]);
    }

    float o[8][4];
#pragma unroll
    for (int dt = 0; dt < 8; dt++)
#pragma unroll
        for (int i = 0; i < 4; i++) o[dt][i] = 0.f;
    float m0 = -1e30f, m1 = -1e30f, l0 = 0.f, l1 = 0.f;

    // prefetch tile 0
    float4 kr[4], vr[4];
#pragma unroll
    for (int q = 0; q < 4; q++) {
        kr[q] = *(const float4*)(kbase + q * 4);
        vr[q] = *(const float4*)(vbase + q * 4);
    }

    for (int kvt = 0; kvt < LL / 64; kvt++) {
        const int buf = kvt & 1;
        float* Ks = sm + KS_OFF + buf * KBUF;
        float* Vs = sm + VS_OFF + buf * VBUF;

        // --- store staged tile (K pair-permuted, V straight; tf32) ---
        {
            float* krow = &Ks[sr * KSTR];
            float* vrow = &Vs[sr * VSTR];
#pragma unroll
            for (int q = 0; q < 4; q++) {
                int d0 = sc + q * 4;
                float* kd = krow + (d0 & ~7) + ((d0 >> 2) & 1);
                kd[0] = tf32f(kr[q].x); kd[2] = tf32f(kr[q].y);
                kd[4] = tf32f(kr[q].z); kd[6] = tf32f(kr[q].w);
                float4 vv;
                vv.x = tf32f(vr[q].x); vv.y = tf32f(vr[q].y);
                vv.z = tf32f(vr[q].z); vv.w = tf32f(vr[q].w);
                *(float4*)(vrow + d0) = vv;
            }
        }

        // --- prefetch next tile (overlaps barrier + compute) ---
        if (kvt + 1 < LL / 64) {
#pragma unroll
            for (int q = 0; q < 4; q++) {
                kr[q] = *(const float4*)(kbase + (size_t)(kvt + 1) * 64 * DH + q * 4);
                vr[q] = *(const float4*)(vbase + (kvt + 1) * 64 + q * 4);
            }
        }

        __syncthreads();   // stores(t) visible; also orders reads(t-1) vs stores(t+1)

        // --- QK^T: S frags (rows r0, r0+8) ---
        float s[8][4];
#pragma unroll
        for (int nt = 0; nt < 8; nt++)
#pragma unroll
            for (int i = 0; i < 4; i++) s[nt][i] = 0.f;
#pragma unroll
        for (int kt = 0; kt < 8; kt++) {
#pragma unroll
            for (int nt = 0; nt < 8; nt++) {
                uint2 b = *(const uint2*)&Ks[(nt * 8 + g) * KSTR + kt * 8 + 2 * cg];
                mma_tf32(s[nt], qa[kt], b.x, b.y);
            }
        }

        // --- online softmax (P stays in registers) ---
        float mt0 = -1e30f, mt1 = -1e30f;
#pragma unroll
        for (int nt = 0; nt < 8; nt++) {
            mt0 = fmaxf(mt0, fmaxf(s[nt][0], s[nt][1]));
            mt1 = fmaxf(mt1, fmaxf(s[nt][2], s[nt][3]));
        }
        mt0 = fmaxf(mt0, __shfl_xor_sync(0xffffffffu, mt0, 1));
        mt0 = fmaxf(mt0, __shfl_xor_sync(0xffffffffu, mt0, 2));
        mt1 = fmaxf(mt1, __shfl_xor_sync(0xffffffffu, mt1, 1));
        mt1 = fmaxf(mt1, __shfl_xor_sync(0xffffffffu, mt1, 2));

        const float mn0 = fmaxf(m0, mt0);
        const float mn1 = fmaxf(m1, mt1);
        const float a0 = __expf(m0 - mn0);
        const float a1 = __expf(m1 - mn1);
        l0 *= a0; l1 *= a1;
#pragma unroll
        for (int dt = 0; dt < 8; dt++) {
            o[dt][0] *= a0; o[dt][1] *= a0;
            o[dt][2] *= a1; o[dt][3] *= a1;
        }

        uint32_t pa[8][4];   // A-frags for PV: {p00, p10, p01, p11}
        float ps0 = 0.f, ps1 = 0.f;
#pragma unroll
        for (int nt = 0; nt < 8; nt++) {
            float p00 = __expf(s[nt][0] - mn0);
            float p01 = __expf(s[nt][1] - mn0);
            float p10 = __expf(s[nt][2] - mn1);
            float p11 = __expf(s[nt][3] - mn1);
            ps0 += p00 + p01;
            ps1 += p10 + p11;
            pa[nt][0] = tf32bits(p00);
            pa[nt][1] = tf32bits(p10);
            pa[nt][2] = tf32bits(p01);
            pa[nt][3] = tf32bits(p11);
        }
        ps0 += __shfl_xor_sync(0xffffffffu, ps0, 1);
        ps0 += __shfl_xor_sync(0xffffffffu, ps0, 2);
        ps1 += __shfl_xor_sync(0xffffffffu, ps1, 1);
        ps1 += __shfl_xor_sync(0xffffffffu, ps1, 2);
        l0 += ps0; l1 += ps1;
        m0 = mn0; m1 = mn1;

        // --- P @ V (Vs straight layout pairs j=2cg,2cg+1 with P C-frag cols) ---
#pragma unroll
        for (int kt = 0; kt < 8; kt++) {
#pragma unroll
            for (int dt = 0; dt < 8; dt++) {
                uint2 b = *(const uint2*)&Vs[(dt * 8 + g) * VSTR + kt * 8 + 2 * cg];
                mma_tf32(o[dt], pa[kt], b.x, b.y);
            }
        }
    }

    // --- epilogue: divide by l, store to (b, l, h*64+d) ---
    const float il0 = 1.f / l0;
    const float il1 = 1.f / l1;
    const int b = bh >> 4, h = bh & (HH - 1);
    const int lq0 = q0 + r0;
    float* ob0 = O + ((size_t)(b * LL + lq0)) * DD + h * DH;
    float* ob1 = O + ((size_t)(b * LL + lq0 + 8)) * DD + h * DH;
#pragma unroll
    for (int dt = 0; dt < 8; dt++) {
        float2 v0 = make_float2(o[dt][0] * il0, o[dt][1] * il0);
        float2 v1 = make_float2(o[dt][2] * il1, o[dt][3] * il1);
        *(float2*)(ob0 + dt * 8 + 2 * cg) = v0;
        *(float2*)(ob1 + dt * 8 + 2 * cg) = v1;
    }
}

// ============================================================
extern "C" void kernel_launch(void* const* d_in, const int* in_sizes, int n_in,
                              void* d_out, int out_size) {
    const float* x      = (const float*)d_in[0];
    const float* rope   = (const float*)d_in[1];
    const float* w_qkv  = (const float*)d_in[2];
    const float* w_proj = (const float*)d_in[3];
    const float* qw     = (const float*)d_in[4];
    const float* kw     = (const float*)d_in[5];
    float* out = (float*)d_out;

    float *qkv, *Q, *K, *V, *O;
    cudaGetSymbolAddress((void**)&qkv, g_qkv);
    cudaGetSymbolAddress((void**)&Q, g_q);
    cudaGetSymbolAddress((void**)&K, g_k);
    cudaGetSymbolAddress((void**)&V, g_v);
    cudaGetSymbolAddress((void**)&O, g_o);

    cudaFuncSetAttribute(attn_mma, cudaFuncAttributeMaxDynamicSharedMemorySize, ATT_SMEM);

    // 1) qkv = x @ w_qkv^T
    sgemm_nt_f2<<<dim3(3 * DD / GBN, MTOT / GBM), 256>>>(x, w_qkv, qkv, MTOT, 3 * DD, DD);

    // 2) rmsnorm + rope + head split (q pre-scaled; V transposed)
    norm_rope_split<<<(MTOT * HH) / 8, 256>>>(qkv, rope, qw, kw, Q, K, V);

    // 3) attention (tf32 mma, P-in-registers, double-buffered) -> g_o
    attn_mma<<<dim3(LL / 128, BB * HH), 256, ATT_SMEM>>>(Q, K, V, O);

    // 4) out = O @ w_proj^T
    sgemm_nt_f2<<<dim3(DD / GBN, MTOT / GBM), 256>>>(O, w_proj, out, MTOT, DD, DD);
}

// round 10
// speedup vs baseline: 2.3403x; 1.1780x over previous
#include <cuda_runtime.h>
#include <cuda_bf16.h>
#include <cstdint>

// Problem dims (fixed by the reference)
#define BB 2
#define LL 2048
#define DD 1024
#define HH 16
#define DH 64
#define MTOT (BB*LL)        // 4096
#define KP   (DD/2)         // 512 bf16-pairs along K

typedef unsigned long long ull;

// ---------------- tf32 mma helpers (sm_80+ base target) ----------------
__device__ __forceinline__ uint32_t tf32bits(float f) {
    uint32_t r; asm("cvt.rna.tf32.f32 %0, %1;" : "=r"(r) : "f"(f)); return r;
}
__device__ __forceinline__ float tf32f(float f) {
    return __uint_as_float(tf32bits(f));
}
__device__ __forceinline__ void mma_tf32(float c[4], const uint32_t a[4],
                                         uint32_t b0, uint32_t b1) {
    asm volatile(
        "mma.sync.aligned.m16n8k8.row.col.f32.tf32.tf32.f32 "
        "{%0,%1,%2,%3}, {%4,%5,%6,%7}, {%8,%9}, {%0,%1,%2,%3};"
        : "+f"(c[0]), "+f"(c[1]), "+f"(c[2]), "+f"(c[3])
        : "r"(a[0]), "r"(a[1]), "r"(a[2]), "r"(a[3]), "r"(b0), "r"(b1));
}
__device__ __forceinline__ void mma_bf16(float c[4], const uint32_t a[4],
                                         uint32_t b0, uint32_t b1) {
    asm volatile(
        "mma.sync.aligned.m16n8k16.row.col.f32.bf16.bf16.f32 "
        "{%0,%1,%2,%3}, {%4,%5,%6,%7}, {%8,%9}, {%0,%1,%2,%3};"
        : "+f"(c[0]), "+f"(c[1]), "+f"(c[2]), "+f"(c[3])
        : "r"(a[0]), "r"(a[1]), "r"(a[2]), "r"(a[3]), "r"(b0), "r"(b1));
}

// -------- scratch (static device globals; no allocation allowed) --------
__device__ float g_qkv[(size_t)MTOT * 3 * DD];          // (B*L, 3072)
__device__ float g_q[(size_t)BB * HH * LL * DH];        // (b,h,l,d)
__device__ float g_k[(size_t)BB * HH * LL * DH];
__device__ float g_v[(size_t)BB * HH * LL * DH];        // TRANSPOSED: (b,h,d,l)
__device__ float g_o[(size_t)MTOT * DD];                // (b,l, h*64+d)
// split-bf16 packed pair arrays (u32 = two bf16, low = even k)
__device__ uint32_t g_xb[(size_t)MTOT * KP];
__device__ uint32_t g_xs[(size_t)MTOT * KP];
__device__ uint32_t g_wqb[(size_t)3 * DD * KP];
__device__ uint32_t g_wqs[(size_t)3 * DD * KP];
__device__ uint32_t g_wpb[(size_t)DD * KP];
__device__ uint32_t g_wps[(size_t)DD * KP];
__device__ uint32_t g_ob[(size_t)MTOT * KP];
__device__ uint32_t g_os[(size_t)MTOT * KP];

// ============================================================
// fp32 -> split bf16 pairs (big + small), packed 2/u32.
// ============================================================
__device__ __forceinline__ uint32_t packpair(float x0, float x1, uint32_t& small) {
    __nv_bfloat16 h0 = __float2bfloat16(x0);
    __nv_bfloat16 h1 = __float2bfloat16(x1);
    float r0 = x0 - __bfloat162float(h0);
    float r1 = x1 - __bfloat162float(h1);
    __nv_bfloat16 e0 = __float2bfloat16(r0);
    __nv_bfloat16 e1 = __float2bfloat16(r1);
    small = ((uint32_t)__bfloat16_as_ushort(e1) << 16) | __bfloat16_as_ushort(e0);
    return ((uint32_t)__bfloat16_as_ushort(h1) << 16) | __bfloat16_as_ushort(h0);
}

__global__ __launch_bounds__(256)
void split_bf16(const float* __restrict__ X, uint32_t* __restrict__ Xb,
                uint32_t* __restrict__ Xs, int n4) {
    int i = blockIdx.x * blockDim.x + threadIdx.x;
    if (i >= n4) return;
    float4 v = ((const float4*)X)[i];
    uint32_t s0, s1;
    uint32_t b0 = packpair(v.x, v.y, s0);
    uint32_t b1 = packpair(v.z, v.w, s1);
    ((uint2*)Xb)[i] = make_uint2(b0, b1);
    ((uint2*)Xs)[i] = make_uint2(s0, s1);
}

// ============================================================
// Split-bf16 GEMM: C[M][N] = A[M][K] * B[N][K]^T
// using D = Ab*Bb + Ab*Bs + As*Bb  (error ~2^-16).
// 128x128x32 tile, 256 thr, warp tile 64x32 (2x4 warp grid).
// Smem pair-permuted: within each group of 8 pairs,
// pair h*4+c -> slot c*2+h, so frags load as single LDS.64.
// ============================================================
#define PSTR 20   // smem row stride in u32 (16 pairs + pad; 80B, 16B-aligned)

__global__ __launch_bounds__(256)
void sgemm_bfx3(const uint32_t* __restrict__ Ab, const uint32_t* __restrict__ As,
                const uint32_t* __restrict__ Bb, const uint32_t* __restrict__ Bs,
                float* __restrict__ C, int M, int N, int Kp) {
    __shared__ uint32_t SAb[128 * PSTR];
    __shared__ uint32_t SAs[128 * PSTR];
    __shared__ uint32_t SBb[128 * PSTR];
    __shared__ uint32_t SBs[128 * PSTR];

    const int tid  = threadIdx.x;
    const int w    = tid >> 5;
    const int lane = tid & 31;
    const int g    = lane >> 2;
    const int cg   = lane & 3;
    const int wm   = w >> 2;          // 0..1
    const int wn   = w & 3;           // 0..3
    const int m0 = blockIdx.y * 128;
    const int n0 = blockIdx.x * 128;

    const int row = tid >> 1;         // 0..127
    const int kh  = tid & 1;          // half-chunk (8 pairs)
    const uint32_t* apb = Ab + (size_t)(m0 + row) * Kp + kh * 8;
    const uint32_t* aps = As + (size_t)(m0 + row) * Kp + kh * 8;
    const uint32_t* bpb = Bb + (size_t)(n0 + row) * Kp + kh * 8;
    const uint32_t* bps = Bs + (size_t)(n0 + row) * Kp + kh * 8;

    float c[4][4][4];
#pragma unroll
    for (int mi = 0; mi < 4; mi++)
#pragma unroll
        for (int ni = 0; ni < 4; ni++)
#pragma unroll
            for (int i = 0; i < 4; i++) c[mi][ni][i] = 0.f;

    // prefetch chunk 0 (each thread: 8 pairs from each of 4 arrays)
    uint4 pab0, pab1, pas0, pas1, pbb0, pbb1, pbs0, pbs1;
    pab0 = *(const uint4*)(apb);     pab1 = *(const uint4*)(apb + 4);
    pas0 = *(const uint4*)(aps);     pas1 = *(const uint4*)(aps + 4);
    pbb0 = *(const uint4*)(bpb);     pbb1 = *(const uint4*)(bpb + 4);
    pbs0 = *(const uint4*)(bps);     pbs1 = *(const uint4*)(bps + 4);

    const int nch = Kp / 16;
    for (int ch = 0; ch < nch; ch++) {
        // permuted store: slots {p0,p4,p1,p5} {p2,p6,p3,p7}
        {
            uint32_t* d;
            d = &SAb[row * PSTR + kh * 8];
            *(uint4*)d       = make_uint4(pab0.x, pab1.x, pab0.y, pab1.y);
            *(uint4*)(d + 4) = make_uint4(pab0.z, pab1.z, pab0.w, pab1.w);
            d = &SAs[row * PSTR + kh * 8];
            *(uint4*)d       = make_uint4(pas0.x, pas1.x, pas0.y, pas1.y);
            *(uint4*)(d + 4) = make_uint4(pas0.z, pas1.z, pas0.w, pas1.w);
            d = &SBb[row * PSTR + kh * 8];
            *(uint4*)d       = make_uint4(pbb0.x, pbb1.x, pbb0.y, pbb1.y);
            *(uint4*)(d + 4) = make_uint4(pbb0.z, pbb1.z, pbb0.w, pbb1.w);
            d = &SBs[row * PSTR + kh * 8];
            *(uint4*)d       = make_uint4(pbs0.x, pbs1.x, pbs0.y, pbs1.y);
            *(uint4*)(d + 4) = make_uint4(pbs0.z, pbs1.z, pbs0.w, pbs1.w);
        }
        __syncthreads();

        // prefetch next chunk
        if (ch + 1 < nch) {
            const int o = (ch + 1) * 16;
            pab0 = *(const uint4*)(apb + o);     pab1 = *(const uint4*)(apb + o + 4);
            pas0 = *(const uint4*)(aps + o);     pas1 = *(const uint4*)(aps + o + 4);
            pbb0 = *(const uint4*)(bpb + o);     pbb1 = *(const uint4*)(bpb + o + 4);
            pbs0 = *(const uint4*)(bps + o);     pbs1 = *(const uint4*)(bps + o + 4);
        }

#pragma unroll
        for (int ks = 0; ks < 2; ks++) {
            uint2 fbb[4], fbs[4];
#pragma unroll
            for (int ni = 0; ni < 4; ni++) {
                const int br = (wn * 32 + ni * 8 + g) * PSTR + ks * 8 + 2 * cg;
                fbb[ni] = *(const uint2*)&SBb[br];
                fbs[ni] = *(const uint2*)&SBs[br];
            }
#pragma unroll
            for (int mi = 0; mi < 4; mi++) {
                const int r = (wm * 64 + mi * 16 + g) * PSTR + ks * 8 + 2 * cg;
                uint2 a0 = *(const uint2*)&SAb[r];
                uint2 a1 = *(const uint2*)&SAb[r + 8 * PSTR];
                uint2 s0 = *(const uint2*)&SAs[r];
                uint2 s1 = *(const uint2*)&SAs[r + 8 * PSTR];
                uint32_t fab[4] = {a0.x, a1.x, a0.y, a1.y};
                uint32_t fas[4] = {s0.x, s1.x, s0.y, s1.y};
#pragma unroll
                for (int ni = 0; ni < 4; ni++) {
                    mma_bf16(c[mi][ni], fab, fbb[ni].x, fbb[ni].y);
                    mma_bf16(c[mi][ni], fab, fbs[ni].x, fbs[ni].y);
                    mma_bf16(c[mi][ni], fas, fbb[ni].x, fbb[ni].y);
                }
            }
        }
        __syncthreads();
    }

    // epilogue
#pragma unroll
    for (int mi = 0; mi < 4; mi++) {
        const int r = m0 + wm * 64 + mi * 16 + g;
#pragma unroll
        for (int ni = 0; ni < 4; ni++) {
            const int cc = n0 + wn * 32 + ni * 8 + 2 * cg;
            *(float2*)&C[(size_t)r * N + cc]       = make_float2(c[mi][ni][0], c[mi][ni][1]);
            *(float2*)&C[(size_t)(r + 8) * N + cc] = make_float2(c[mi][ni][2], c[mi][ni][3]);
        }
    }
}

// ============================================================
// rmsnorm + RoPE + head split.  One warp per (b,l,h).
// q pre-scaled by 0.125.  V written TRANSPOSED: (b,h,d,l).
// ============================================================
__global__ __launch_bounds__(256)
void norm_rope_split(const float* __restrict__ qkv, const float* __restrict__ rope,
                     const float* __restrict__ qw, const float* __restrict__ kw,
                     float* __restrict__ Q, float* __restrict__ K, float* __restrict__ Vt) {
    const int warp = (blockIdx.x * blockDim.x + threadIdx.x) >> 5;
    const int lane = threadIdx.x & 31;
    const int h  = warp & (HH - 1);
    const int bl = warp >> 4;               // b*L + l
    const int l  = bl & (LL - 1);
    const int b  = bl >> 11;

    const float* base = qkv + (size_t)bl * (3 * DD);
    const float c = rope[l * DH + lane * 2];
    const float s = rope[l * DH + lane * 2 + 1];
    const size_t obase = ((size_t)(b * HH + h) * LL + l) * DH;

    // ---- Q ----
    {
        float2 x = *(const float2*)(base + h * DH + lane * 2);
        float ss = x.x * x.x + x.y * x.y;
#pragma unroll
        for (int o = 16; o; o >>= 1) ss += __shfl_xor_sync(0xffffffffu, ss, o);
        float inv = rsqrtf(ss * (1.f / DH) + 1e-6f);
        float e = x.x * inv * qw[lane * 2];
        float o_ = x.y * inv * qw[lane * 2 + 1];
        Q[obase + lane * 2]     = 0.125f * (e * c - o_ * s);
        Q[obase + lane * 2 + 1] = 0.125f * (e * s + o_ * c);
    }
    // ---- K ----
    {
        float2 x = *(const float2*)(base + DD + h * DH + lane * 2);
        float ss = x.x * x.x + x.y * x.y;
#pragma unroll
        for (int o = 16; o; o >>= 1) ss += __shfl_xor_sync(0xffffffffu, ss, o);
        float inv = rsqrtf(ss * (1.f / DH) + 1e-6f);
        float e = x.x * inv * kw[lane * 2];
        float o_ = x.y * inv * kw[lane * 2 + 1];
        K[obase + lane * 2]     = e * c - o_ * s;
        K[obase + lane * 2 + 1] = e * s + o_ * c;
    }
    // ---- V transposed write: Vt[(b,h), d, l] ----
    {
        float2 v = *(const float2*)(base + 2 * DD + h * DH + lane * 2);
        const size_t vb = ((size_t)(b * HH + h) * DH + lane * 2) * LL + l;
        Vt[vb]      = v.x;
        Vt[vb + LL] = v.y;
    }
}

// ============================================================
// Flash attention, tf32 mma.sync (m16n8k8), P kept in registers.
// (proven round-8 kernel, unchanged)
// ============================================================
#define KSTR 66
#define VSTR 68
#define KBUF (64 * KSTR)
#define VBUF (64 * VSTR)
#define KS_OFF 0
#define VS_OFF (2 * KBUF)
#define ATT_SMEM ((2 * KBUF + 2 * VBUF) * 4)   // 68608 B

__global__ __launch_bounds__(256)
void attn_mma(const float* __restrict__ Qg, const float* __restrict__ Kg,
              const float* __restrict__ Vt, float* __restrict__ O) {
    extern __shared__ float sm[];

    const int tid  = threadIdx.x;
    const int w    = tid >> 5;
    const int lane = tid & 31;
    const int g    = lane >> 2;
    const int cg   = lane & 3;
    const int bh   = blockIdx.y;
    const int q0   = blockIdx.x * 128;
    const int r0   = w * 16 + g;

    const int sr = tid >> 2;
    const int sc = (tid & 3) * 16;
    const float* kbase = Kg + ((size_t)bh * LL + sr) * DH + sc;
    const float* vbase = Vt + ((size_t)bh * DH + sr) * LL + sc;

    const float* qbase = Qg + ((size_t)bh * LL + q0) * DH;
    uint32_t qa[8][4];
#pragma unroll
    for (int kt = 0; kt < 8; kt++) {
        qa[kt][0] = tf32bits(qbase[(size_t)r0 * DH + kt * 8 + cg]);
        qa[kt][1] = tf32bits(qbase[(size_t)(r0 + 8) * DH + kt * 8 + cg]);
        qa[kt][2] = tf32bits(qbase[(size_t)r0 * DH + kt * 8 + cg + 4]);
        qa[kt][3] = tf32bits(qbase[(size_t)(r0 + 8) * DH + kt * 8 + cg + 4]);
    }

    float o[8][4];
#pragma unroll
    for (int dt = 0; dt < 8; dt++)
#pragma unroll
        for (int i = 0; i < 4; i++) o[dt][i] = 0.f;
    float m0 = -1e30f, m1 = -1e30f, l0 = 0.f, l1 = 0.f;

    float4 kr[4], vr[4];
#pragma unroll
    for (int q = 0; q < 4; q++) {
        kr[q] = *(const float4*)(kbase + q * 4);
        vr[q] = *(const float4*)(vbase + q * 4);
    }

    for (int kvt = 0; kvt < LL / 64; kvt++) {
        const int buf = kvt & 1;
        float* Ks = sm + KS_OFF + buf * KBUF;
        float* Vs = sm + VS_OFF + buf * VBUF;

        {
            float* krow = &Ks[sr * KSTR];
            float* vrow = &Vs[sr * VSTR];
#pragma unroll
            for (int q = 0; q < 4; q++) {
                int d0 = sc + q * 4;
                float* kd = krow + (d0 & ~7) + ((d0 >> 2) & 1);
                kd[0] = tf32f(kr[q].x); kd[2] = tf32f(kr[q].y);
                kd[4] = tf32f(kr[q].z); kd[6] = tf32f(kr[q].w);
                float4 vv;
                vv.x = tf32f(vr[q].x); vv.y = tf32f(vr[q].y);
                vv.z = tf32f(vr[q].z); vv.w = tf32f(vr[q].w);
                *(float4*)(vrow + d0) = vv;
            }
        }

        if (kvt + 1 < LL / 64) {
#pragma unroll
            for (int q = 0; q < 4; q++) {
                kr[q] = *(const float4*)(kbase + (size_t)(kvt + 1) * 64 * DH + q * 4);
                vr[q] = *(const float4*)(vbase + (kvt + 1) * 64 + q * 4);
            }
        }

        __syncthreads();

        float s[8][4];
#pragma unroll
        for (int nt = 0; nt < 8; nt++)
#pragma unroll
            for (int i = 0; i < 4; i++) s[nt][i] = 0.f;
#pragma unroll
        for (int kt = 0; kt < 8; kt++) {
#pragma unroll
            for (int nt = 0; nt < 8; nt++) {
                uint2 b = *(const uint2*)&Ks[(nt * 8 + g) * KSTR + kt * 8 + 2 * cg];
                mma_tf32(s[nt], qa[kt], b.x, b.y);
            }
        }

        float mt0 = -1e30f, mt1 = -1e30f;
#pragma unroll
        for (int nt = 0; nt < 8; nt++) {
            mt0 = fmaxf(mt0, fmaxf(s[nt][0], s[nt][1]));
            mt1 = fmaxf(mt1, fmaxf(s[nt][2], s[nt][3]));
        }
        mt0 = fmaxf(mt0, __shfl_xor_sync(0xffffffffu, mt0, 1));
        mt0 = fmaxf(mt0, __shfl_xor_sync(0xffffffffu, mt0, 2));
        mt1 = fmaxf(mt1, __shfl_xor_sync(0xffffffffu, mt1, 1));
        mt1 = fmaxf(mt1, __shfl_xor_sync(0xffffffffu, mt1, 2));

        const float mn0 = fmaxf(m0, mt0);
        const float mn1 = fmaxf(m1, mt1);
        const float a0 = __expf(m0 - mn0);
        const float a1 = __expf(m1 - mn1);
        l0 *= a0; l1 *= a1;
#pragma unroll
        for (int dt = 0; dt < 8; dt++) {
            o[dt][0] *= a0; o[dt][1] *= a0;
            o[dt][2] *= a1; o[dt][3] *= a1;
        }

        uint32_t pa[8][4];
        float ps0 = 0.f, ps1 = 0.f;
#pragma unroll
        for (int nt = 0; nt < 8; nt++) {
            float p00 = __expf(s[nt][0] - mn0);
            float p01 = __expf(s[nt][1] - mn0);
            float p10 = __expf(s[nt][2] - mn1);
            float p11 = __expf(s[nt][3] - mn1);
            ps0 += p00 + p01;
            ps1 += p10 + p11;
            pa[nt][0] = tf32bits(p00);
            pa[nt][1] = tf32bits(p10);
            pa[nt][2] = tf32bits(p01);
            pa[nt][3] = tf32bits(p11);
        }
        ps0 += __shfl_xor_sync(0xffffffffu, ps0, 1);
        ps0 += __shfl_xor_sync(0xffffffffu, ps0, 2);
        ps1 += __shfl_xor_sync(0xffffffffu, ps1, 1);
        ps1 += __shfl_xor_sync(0xffffffffu, ps1, 2);
        l0 += ps0; l1 += ps1;
        m0 = mn0; m1 = mn1;

#pragma unroll
        for (int kt = 0; kt < 8; kt++) {
#pragma unroll
            for (int dt = 0; dt < 8; dt++) {
                uint2 b = *(const uint2*)&Vs[(dt * 8 + g) * VSTR + kt * 8 + 2 * cg];
                mma_tf32(o[dt], pa[kt], b.x, b.y);
            }
        }
    }

    const float il0 = 1.f / l0;
    const float il1 = 1.f / l1;
    const int b = bh >> 4, h = bh & (HH - 1);
    const int lq0 = q0 + r0;
    float* ob0 = O + ((size_t)(b * LL + lq0)) * DD + h * DH;
    float* ob1 = O + ((size_t)(b * LL + lq0 + 8)) * DD + h * DH;
#pragma unroll
    for (int dt = 0; dt < 8; dt++) {
        float2 v0 = make_float2(o[dt][0] * il0, o[dt][1] * il0);
        float2 v1 = make_float2(o[dt][2] * il1, o[dt][3] * il1);
        *(float2*)(ob0 + dt * 8 + 2 * cg) = v0;
        *(float2*)(ob1 + dt * 8 + 2 * cg) = v1;
    }
}

// ============================================================
extern "C" void kernel_launch(void* const* d_in, const int* in_sizes, int n_in,
                              void* d_out, int out_size) {
    const float* x      = (const float*)d_in[0];
    const float* rope   = (const float*)d_in[1];
    const float* w_qkv  = (const float*)d_in[2];
    const float* w_proj = (const float*)d_in[3];
    const float* qw     = (const float*)d_in[4];
    const float* kw     = (const float*)d_in[5];
    float* out = (float*)d_out;

    float *qkv, *Q, *K, *V, *O;
    uint32_t *xb, *xs, *wqb, *wqs, *wpb, *wps, *ob, *os;
    cudaGetSymbolAddress((void**)&qkv, g_qkv);
    cudaGetSymbolAddress((void**)&Q, g_q);
    cudaGetSymbolAddress((void**)&K, g_k);
    cudaGetSymbolAddress((void**)&V, g_v);
    cudaGetSymbolAddress((void**)&O, g_o);
    cudaGetSymbolAddress((void**)&xb, g_xb);
    cudaGetSymbolAddress((void**)&xs, g_xs);
    cudaGetSymbolAddress((void**)&wqb, g_wqb);
    cudaGetSymbolAddress((void**)&wqs, g_wqs);
    cudaGetSymbolAddress((void**)&wpb, g_wpb);
    cudaGetSymbolAddress((void**)&wps, g_wps);
    cudaGetSymbolAddress((void**)&ob, g_ob);
    cudaGetSymbolAddress((void**)&os, g_os);

    cudaFuncSetAttribute(attn_mma, cudaFuncAttributeMaxDynamicSharedMemorySize, ATT_SMEM);

    // 0) split fp32 -> bf16 big/small pair arrays
    const int n4x = MTOT * DD / 4;          // 1,048,576
    const int n4q = 3 * DD * DD / 4;        //   786,432
    const int n4p = DD * DD / 4;            //   262,144
    split_bf16<<<(n4x + 255) / 256, 256>>>(x, xb, xs, n4x);
    split_bf16<<<(n4q + 255) / 256, 256>>>(w_qkv, wqb, wqs, n4q);
    split_bf16<<<(n4p + 255) / 256, 256>>>(w_proj, wpb, wps, n4p);

    // 1) qkv = x @ w_qkv^T   [bf16x3 tensor-core GEMM]
    sgemm_bfx3<<<dim3(3 * DD / 128, MTOT / 128), 256>>>(xb, xs, wqb, wqs, qkv, MTOT, 3 * DD, KP);

    // 2) rmsnorm + rope + head split (q pre-scaled; V transposed)
    norm_rope_split<<<(MTOT * HH) / 8, 256>>>(qkv, rope, qw, kw, Q, K, V);

    // 3) attention (tf32 mma, P-in-registers, double-buffered) -> g_o
    attn_mma<<<dim3(LL / 128, BB * HH), 256, ATT_SMEM>>>(Q, K, V, O);

    // 4) out = O @ w_proj^T  [bf16x3 tensor-core GEMM]
    split_bf16<<<(n4x + 255) / 256, 256>>>(O, ob, os, n4x);
    sgemm_bfx3<<<dim3(DD / 128, MTOT / 128), 256>>>(ob, os, wpb, wps, out, MTOT, DD, KP);
}

// round 14
// speedup vs baseline: 2.4879x; 1.0631x over previous
#include <cuda_runtime.h>
#include <cuda_bf16.h>
#include <cstdint>

// Problem dims (fixed by the reference)
#define BB 2
#define LL 2048
#define DD 1024
#define HH 16
#define DH 64
#define MTOT (BB*LL)        // 4096
#define KP   (DD/2)         // 512 bf16-pairs along K

typedef unsigned long long ull;

// ---------------- mma helpers (sm_80+ base target) ----------------
__device__ __forceinline__ uint32_t tf32bits(float f) {
    uint32_t r; asm("cvt.rna.tf32.f32 %0, %1;" : "=r"(r) : "f"(f)); return r;
}
__device__ __forceinline__ float tf32f(float f) {
    return __uint_as_float(tf32bits(f));
}
__device__ __forceinline__ void mma_tf32(float c[4], const uint32_t a[4],
                                         uint32_t b0, uint32_t b1) {
    asm volatile(
        "mma.sync.aligned.m16n8k8.row.col.f32.tf32.tf32.f32 "
        "{%0,%1,%2,%3}, {%4,%5,%6,%7}, {%8,%9}, {%0,%1,%2,%3};"
        : "+f"(c[0]), "+f"(c[1]), "+f"(c[2]), "+f"(c[3])
        : "r"(a[0]), "r"(a[1]), "r"(a[2]), "r"(a[3]), "r"(b0), "r"(b1));
}
__device__ __forceinline__ void mma_bf16(float c[4], const uint32_t a[4],
                                         uint32_t b0, uint32_t b1) {
    asm volatile(
        "mma.sync.aligned.m16n8k16.row.col.f32.bf16.bf16.f32 "
        "{%0,%1,%2,%3}, {%4,%5,%6,%7}, {%8,%9}, {%0,%1,%2,%3};"
        : "+f"(c[0]), "+f"(c[1]), "+f"(c[2]), "+f"(c[3])
        : "r"(a[0]), "r"(a[1]), "r"(a[2]), "r"(a[3]), "r"(b0), "r"(b1));
}
__device__ __forceinline__ uint32_t smem_u32(const void* p) {
    uint32_t a;
    asm("{ .reg .u64 t; cvta.to.shared.u64 t, %1; cvt.u32.u64 %0, t; }" : "=r"(a) : "l"(p));
    return a;
}
__device__ __forceinline__ void cp16(uint32_t dst, const void* src) {
    asm volatile("cp.async.ca.shared.global [%0], [%1], 16;" :: "r"(dst), "l"(src) : "memory");
}
#define CP_COMMIT() asm volatile("cp.async.commit_group;" ::: "memory")
#define CP_WAIT(n)  asm volatile("cp.async.wait_group %0;" :: "n"(n) : "memory")

// -------- scratch (static device globals; no allocation allowed) --------
__device__ float g_qkv[(size_t)MTOT * 3 * DD];          // (B*L, 3072)
__device__ float g_q[(size_t)BB * HH * LL * DH];        // (b,h,l,d)
__device__ float g_k[(size_t)BB * HH * LL * DH];
__device__ float g_v[(size_t)BB * HH * LL * DH];        // TRANSPOSED: (b,h,d,l)
// split-bf16 packed pair arrays (u32 = two bf16), PRE-PERMUTED:
// within each group of 8 u32 along K, pair j sits at slot (j%4)*2 + j/4.
__device__ uint32_t g_xb[(size_t)MTOT * KP];
__device__ uint32_t g_xs[(size_t)MTOT * KP];
__device__ uint32_t g_wqb[(size_t)3 * DD * KP];
__device__ uint32_t g_wqs[(size_t)3 * DD * KP];
__device__ uint32_t g_wpb[(size_t)DD * KP];
__device__ uint32_t g_wps[(size_t)DD * KP];
__device__ uint32_t g_ob[(size_t)MTOT * KP];
__device__ uint32_t g_os[(size_t)MTOT * KP];

// ============================================================
// fp32 -> split bf16 pairs (big + small), packed, permuted.
// ============================================================
__device__ __forceinline__ uint32_t packpair(float x0, float x1, uint32_t& small) {
    __nv_bfloat16 h0 = __float2bfloat16(x0);
    __nv_bfloat16 h1 = __float2bfloat16(x1);
    float r0 = x0 - __bfloat162float(h0);
    float r1 = x1 - __bfloat162float(h1);
    __nv_bfloat16 e0 = __float2bfloat16(r0);
    __nv_bfloat16 e1 = __float2bfloat16(r1);
    small = ((uint32_t)__bfloat16_as_ushort(e1) << 16) | __bfloat16_as_ushort(e0);
    return ((uint32_t)__bfloat16_as_ushort(h1) << 16) | __bfloat16_as_ushort(h0);
}

__global__ __launch_bounds__(256)
void split_bf16(const float* __restrict__ X, uint32_t* __restrict__ Xb,
                uint32_t* __restrict__ Xs, int n4) {
    int i = blockIdx.x * blockDim.x + threadIdx.x;
    if (i >= n4) return;
    float4 v = ((const float4*)X)[i];
    uint32_t s0, s1;
    uint32_t b0 = packpair(v.x, v.y, s0);
    uint32_t b1 = packpair(v.z, v.w, s1);
    const int k = 2 * i;                 // u32 pair index (even)
    const int base = k & ~7;
    const int j0 = k & 7;
    const int p0 = ((j0 & 3) << 1) | (j0 >> 2);
    const int j1 = j0 + 1;
    const int p1 = ((j1 & 3) << 1) | (j1 >> 2);
    Xb[base + p0] = b0; Xb[base + p1] = b1;
    Xs[base + p0] = s0; Xs[base + p1] = s1;
}

// ============================================================
// Split-bf16 GEMM: C[M][N] = A[M][K]*B[N][K]^T, D=AbBb+AbBs+AsBb.
// 128x128x32 tile, 256 thr (2 blocks/SM), warp tile 64x32.
// cp.async double-buffered staging from pre-permuted globals.
// ============================================================
#define PSTR 20                 // smem row stride in u32
#define ARR  (128 * PSTR)       // u32 per array
#define STG  (4 * ARR)          // u32 per stage
#define GSMEM (2 * STG * 4)     // 81920 B

__global__ void __launch_bounds__(256, 2)
sgemm_bfx3(const uint32_t* __restrict__ Ab, const uint32_t* __restrict__ As,
           const uint32_t* __restrict__ Bb, const uint32_t* __restrict__ Bs,
           float* __restrict__ C, int M, int N, int Kp) {
    extern __shared__ uint32_t su[];

    const int tid  = threadIdx.x;
    const int w    = tid >> 5;
    const int lane = tid & 31;
    const int g    = lane >> 2;
    const int cg   = lane & 3;
    const int wm   = w >> 2;          // 0..1
    const int wn   = w & 3;           // 0..3
    const int m0 = blockIdx.y * 128;
    const int n0 = blockIdx.x * 128;

    const int row = tid >> 1;         // 0..127
    const int kh  = tid & 1;          // half-chunk (8 u32)
    const uint32_t* pAb = Ab + (size_t)(m0 + row) * Kp + kh * 8;
    const uint32_t* pAs = As + (size_t)(m0 + row) * Kp + kh * 8;
    const uint32_t* pBb = Bb + (size_t)(n0 + row) * Kp + kh * 8;
    const uint32_t* pBs = Bs + (size_t)(n0 + row) * Kp + kh * 8;
    const uint32_t dst0 = smem_u32(su) + (uint32_t)(row * PSTR + kh * 8) * 4;

    float c[4][4][4];
#pragma unroll
    for (int mi = 0; mi < 4; mi++)
#pragma unroll
        for (int ni = 0; ni < 4; ni++)
#pragma unroll
            for (int i = 0; i < 4; i++) c[mi][ni][i] = 0.f;

    const int nch = Kp / 16;

#define ISSUE(ch, st) do {                                             \
        const int off_ = (ch) * 16;                                    \
        uint32_t d_ = dst0 + (uint32_t)(st) * (STG * 4);               \
        cp16(d_,                     pAb + off_);                      \
        cp16(d_ + 16,                pAb + off_ + 4);                  \
        cp16(d_ + ARR * 4,           pAs + off_);                      \
        cp16(d_ + ARR * 4 + 16,      pAs + off_ + 4);                  \
        cp16(d_ + 2 * ARR * 4,       pBb + off_);                      \
        cp16(d_ + 2 * ARR * 4 + 16,  pBb + off_ + 4);                  \
        cp16(d_ + 3 * ARR * 4,       pBs + off_);                      \
        cp16(d_ + 3 * ARR * 4 + 16,  pBs + off_ + 4);                  \
        CP_COMMIT();                                                   \
    } while (0)

    ISSUE(0, 0);
    ISSUE(1, 1);

    for (int ch = 0; ch < nch; ch++) {
        if (ch + 1 < nch) { CP_WAIT(1); } else { CP_WAIT(0); }
        __syncthreads();

        const uint32_t* SAb = su + (ch & 1) * STG;
        const uint32_t* SAs = SAb + ARR;
        const uint32_t* SBb = SAb + 2 * ARR;
        const uint32_t* SBs = SAb + 3 * ARR;

#pragma unroll
        for (int ks = 0; ks < 2; ks++) {
            uint2 fbb[4], fbs[4];
#pragma unroll
            for (int ni = 0; ni < 4; ni++) {
                const int br = (wn * 32 + ni * 8 + g) * PSTR + ks * 8 + 2 * cg;
                fbb[ni] = *(const uint2*)&SBb[br];
                fbs[ni] = *(const uint2*)&SBs[br];
            }
#pragma unroll
            for (int mi = 0; mi < 4; mi++) {
                const int r = (wm * 64 + mi * 16 + g) * PSTR + ks * 8 + 2 * cg;
                uint2 a0 = *(const uint2*)&SAb[r];
                uint2 a1 = *(const uint2*)&SAb[r + 8 * PSTR];
                uint2 s0 = *(const uint2*)&SAs[r];
                uint2 s1 = *(const uint2*)&SAs[r + 8 * PSTR];
                uint32_t fab[4] = {a0.x, a1.x, a0.y, a1.y};
                uint32_t fas[4] = {s0.x, s1.x, s0.y, s1.y};
#pragma unroll
                for (int ni = 0; ni < 4; ni++) {
                    mma_bf16(c[mi][ni], fab, fbb[ni].x, fbb[ni].y);
                    mma_bf16(c[mi][ni], fab, fbs[ni].x, fbs[ni].y);
                    mma_bf16(c[mi][ni], fas, fbb[ni].x, fbb[ni].y);
                }
            }
        }
        __syncthreads();
        if (ch + 2 < nch) ISSUE(ch + 2, ch & 1);
    }
#undef ISSUE

    // epilogue
#pragma unroll
    for (int mi = 0; mi < 4; mi++) {
        const int r = m0 + wm * 64 + mi * 16 + g;
#pragma unroll
        for (int ni = 0; ni < 4; ni++) {
            const int cc = n0 + wn * 32 + ni * 8 + 2 * cg;
            *(float2*)&C[(size_t)r * N + cc]       = make_float2(c[mi][ni][0], c[mi][ni][1]);
            *(float2*)&C[(size_t)(r + 8) * N + cc] = make_float2(c[mi][ni][2], c[mi][ni][3]);
        }
    }
}

// ============================================================
// rmsnorm + RoPE + head split.  One warp per (b,l,h).
// q pre-scaled by 0.125.  V written TRANSPOSED: (b,h,d,l).
// ============================================================
__global__ __launch_bounds__(256)
void norm_rope_split(const float* __restrict__ qkv, const float* __restrict__ rope,
                     const float* __restrict__ qw, const float* __restrict__ kw,
                     float* __restrict__ Q, float* __restrict__ K, float* __restrict__ Vt) {
    const int warp = (blockIdx.x * blockDim.x + threadIdx.x) >> 5;
    const int lane = threadIdx.x & 31;
    const int h  = warp & (HH - 1);
    const int bl = warp >> 4;               // b*L + l
    const int l  = bl & (LL - 1);
    const int b  = bl >> 11;

    const float* base = qkv + (size_t)bl * (3 * DD);
    const float c = rope[l * DH + lane * 2];
    const float s = rope[l * DH + lane * 2 + 1];
    const size_t obase = ((size_t)(b * HH + h) * LL + l) * DH;

    // ---- Q ----
    {
        float2 x = *(const float2*)(base + h * DH + lane * 2);
        float ss = x.x * x.x + x.y * x.y;
#pragma unroll
        for (int o = 16; o; o >>= 1) ss += __shfl_xor_sync(0xffffffffu, ss, o);
        float inv = rsqrtf(ss * (1.f / DH) + 1e-6f);
        float e = x.x * inv * qw[lane * 2];
        float o_ = x.y * inv * qw[lane * 2 + 1];
        Q[obase + lane * 2]     = 0.125f * (e * c - o_ * s);
        Q[obase + lane * 2 + 1] = 0.125f * (e * s + o_ * c);
    }
    // ---- K ----
    {
        float2 x = *(const float2*)(base + DD + h * DH + lane * 2);
        float ss = x.x * x.x + x.y * x.y;
#pragma unroll
        for (int o = 16; o; o >>= 1) ss += __shfl_xor_sync(0xffffffffu, ss, o);
        float inv = rsqrtf(ss * (1.f / DH) + 1e-6f);
        float e = x.x * inv * kw[lane * 2];
        float o_ = x.y * inv * kw[lane * 2 + 1];
        K[obase + lane * 2]     = e * c - o_ * s;
        K[obase + lane * 2 + 1] = e * s + o_ * c;
    }
    // ---- V transposed write: Vt[(b,h), d, l] ----
    {
        float2 v = *(const float2*)(base + 2 * DD + h * DH + lane * 2);
        const size_t vb = ((size_t)(b * HH + h) * DH + lane * 2) * LL + l;
        Vt[vb]      = v.x;
        Vt[vb + LL] = v.y;
    }
}

// ============================================================
// Flash attention, tf32 mma.sync, P-in-registers (round-8 core).
// Epilogue FUSED with split-bf16: writes permuted ob/os directly.
// ============================================================
#define KSTR 66
#define VSTR 68
#define KBUF (64 * KSTR)
#define VBUF (64 * VSTR)
#define KS_OFF 0
#define VS_OFF (2 * KBUF)
#define ATT_SMEM ((2 * KBUF + 2 * VBUF) * 4)   // 68608 B

__global__ __launch_bounds__(256)
void attn_mma(const float* __restrict__ Qg, const float* __restrict__ Kg,
              const float* __restrict__ Vt,
              uint32_t* __restrict__ Ob, uint32_t* __restrict__ Os) {
    extern __shared__ float sm[];

    const int tid  = threadIdx.x;
    const int w    = tid >> 5;
    const int lane = tid & 31;
    const int g    = lane >> 2;
    const int cg   = lane & 3;
    const int bh   = blockIdx.y;
    const int q0   = blockIdx.x * 128;
    const int r0   = w * 16 + g;

    const int sr = tid >> 2;
    const int sc = (tid & 3) * 16;
    const float* kbase = Kg + ((size_t)bh * LL + sr) * DH + sc;
    const float* vbase = Vt + ((size_t)bh * DH + sr) * LL + sc;

    const float* qbase = Qg + ((size_t)bh * LL + q0) * DH;
    uint32_t qa[8][4];
#pragma unroll
    for (int kt = 0; kt < 8; kt++) {
        qa[kt][0] = tf32bits(qbase[(size_t)r0 * DH + kt * 8 + cg]);
        qa[kt][1] = tf32bits(qbase[(size_t)(r0 + 8) * DH + kt * 8 + cg]);
        qa[kt][2] = tf32bits(qbase[(size_t)r0 * DH + kt * 8 + cg + 4]);
        qa[kt][3] = tf32bits(qbase[(size_t)(r0 + 8) * DH + kt * 8 + cg + 4]);
    }

    float o[8][4];
#pragma unroll
    for (int dt = 0; dt < 8; dt++)
#pragma unroll
        for (int i = 0; i < 4; i++) o[dt][i] = 0.f;
    float m0 = -1e30f, m1 = -1e30f, l0 = 0.f, l1 = 0.f;

    float4 kr[4], vr[4];
#pragma unroll
    for (int q = 0; q < 4; q++) {
        kr[q] = *(const float4*)(kbase + q * 4);
        vr[q] = *(const float4*)(vbase + q * 4);
    }

    for (int kvt = 0; kvt < LL / 64; kvt++) {
        const int buf = kvt & 1;
        float* Ks = sm + KS_OFF + buf * KBUF;
        float* Vs = sm + VS_OFF + buf * VBUF;

        {
            float* krow = &Ks[sr * KSTR];
            float* vrow = &Vs[sr * VSTR];
#pragma unroll
            for (int q = 0; q < 4; q++) {
                int d0 = sc + q * 4;
                float* kd = krow + (d0 & ~7) + ((d0 >> 2) & 1);
                kd[0] = tf32f(kr[q].x); kd[2] = tf32f(kr[q].y);
                kd[4] = tf32f(kr[q].z); kd[6] = tf32f(kr[q].w);
                float4 vv;
                vv.x = tf32f(vr[q].x); vv.y = tf32f(vr[q].y);
                vv.z = tf32f(vr[q].z); vv.w = tf32f(vr[q].w);
                *(float4*)(vrow + d0) = vv;
            }
        }

        if (kvt + 1 < LL / 64) {
#pragma unroll
            for (int q = 0; q < 4; q++) {
                kr[q] = *(const float4*)(kbase + (size_t)(kvt + 1) * 64 * DH + q * 4);
                vr[q] = *(const float4*)(vbase + (kvt + 1) * 64 + q * 4);
            }
        }

        __syncthreads();

        float s[8][4];
#pragma unroll
        for (int nt = 0; nt < 8; nt++)
#pragma unroll
            for (int i = 0; i < 4; i++) s[nt][i] = 0.f;
#pragma unroll
        for (int kt = 0; kt < 8; kt++) {
#pragma unroll
            for (int nt = 0; nt < 8; nt++) {
                uint2 b = *(const uint2*)&Ks[(nt * 8 + g) * KSTR + kt * 8 + 2 * cg];
                mma_tf32(s[nt], qa[kt], b.x, b.y);
            }
        }

        float mt0 = -1e30f, mt1 = -1e30f;
#pragma unroll
        for (int nt = 0; nt < 8; nt++) {
            mt0 = fmaxf(mt0, fmaxf(s[nt][0], s[nt][1]));
            mt1 = fmaxf(mt1, fmaxf(s[nt][2], s[nt][3]));
        }
        mt0 = fmaxf(mt0, __shfl_xor_sync(0xffffffffu, mt0, 1));
        mt0 = fmaxf(mt0, __shfl_xor_sync(0xffffffffu, mt0, 2));
        mt1 = fmaxf(mt1, __shfl_xor_sync(0xffffffffu, mt1, 1));
        mt1 = fmaxf(mt1, __shfl_xor_sync(0xffffffffu, mt1, 2));

        const float mn0 = fmaxf(m0, mt0);
        const float mn1 = fmaxf(m1, mt1);
        const float a0 = __expf(m0 - mn0);
        const float a1 = __expf(m1 - mn1);
        l0 *= a0; l1 *= a1;
#pragma unroll
        for (int dt = 0; dt < 8; dt++) {
            o[dt][0] *= a0; o[dt][1] *= a0;
            o[dt][2] *= a1; o[dt][3] *= a1;
        }

        uint32_t pa[8][4];
        float ps0 = 0.f, ps1 = 0.f;
#pragma unroll
        for (int nt = 0; nt < 8; nt++) {
            float p00 = __expf(s[nt][0] - mn0);
            float p01 = __expf(s[nt][1] - mn0);
            float p10 = __expf(s[nt][2] - mn1);
            float p11 = __expf(s[nt][3] - mn1);
            ps0 += p00 + p01;
            ps1 += p10 + p11;
            pa[nt][0] = tf32bits(p00);
            pa[nt][1] = tf32bits(p10);
            pa[nt][2] = tf32bits(p01);
            pa[nt][3] = tf32bits(p11);
        }
        ps0 += __shfl_xor_sync(0xffffffffu, ps0, 1);
        ps0 += __shfl_xor_sync(0xffffffffu, ps0, 2);
        ps1 += __shfl_xor_sync(0xffffffffu, ps1, 1);
        ps1 += __shfl_xor_sync(0xffffffffu, ps1, 2);
        l0 += ps0; l1 += ps1;
        m0 = mn0; m1 = mn1;

#pragma unroll
        for (int kt = 0; kt < 8; kt++) {
#pragma unroll
            for (int dt = 0; dt < 8; dt++) {
                uint2 b = *(const uint2*)&Vs[(dt * 8 + g) * VSTR + kt * 8 + 2 * cg];
                mma_tf32(o[dt], pa[kt], b.x, b.y);
            }
        }
    }

    // --- fused epilogue: divide by l, split to bf16 pairs, permuted store ---
    const float il0 = 1.f / l0;
    const float il1 = 1.f / l1;
    const int b = bh >> 4, h = bh & (HH - 1);
    const size_t rowA = (size_t)(b * LL + q0 + r0);
#pragma unroll
    for (int dt = 0; dt < 8; dt++) {
        const int kp_ = h * 32 + dt * 4 + cg;            // pair index in row
        const int jj = kp_ & 7;
        const int col = (kp_ & ~7) + (((jj & 3) << 1) | (jj >> 2));
        uint32_t sbits, bbits;
        bbits = packpair(o[dt][0] * il0, o[dt][1] * il0, sbits);
        Ob[rowA * KP + col] = bbits;
        Os[rowA * KP + col] = sbits;
        bbits = packpair(o[dt][2] * il1, o[dt][3] * il1, sbits);
        Ob[(rowA + 8) * KP + col] = bbits;
        Os[(rowA + 8) * KP + col] = sbits;
    }
}

// ============================================================
extern "C" void kernel_launch(void* const* d_in, const int* in_sizes, int n_in,
                              void* d_out, int out_size) {
    const float* x      = (const float*)d_in[0];
    const float* rope   = (const float*)d_in[1];
    const float* w_qkv  = (const float*)d_in[2];
    const float* w_proj = (const float*)d_in[3];
    const float* qw     = (const float*)d_in[4];
    const float* kw     = (const float*)d_in[5];
    float* out = (float*)d_out;

    float *qkv, *Q, *K, *V;
    uint32_t *xb, *xs, *wqb, *wqs, *wpb, *wps, *ob, *os;
    cudaGetSymbolAddress((void**)&qkv, g_qkv);
    cudaGetSymbolAddress((void**)&Q, g_q);
    cudaGetSymbolAddress((void**)&K, g_k);
    cudaGetSymbolAddress((void**)&V, g_v);
    cudaGetSymbolAddress((void**)&xb, g_xb);
    cudaGetSymbolAddress((void**)&xs, g_xs);
    cudaGetSymbolAddress((void**)&wqb, g_wqb);
    cudaGetSymbolAddress((void**)&wqs, g_wqs);
    cudaGetSymbolAddress((void**)&wpb, g_wpb);
    cudaGetSymbolAddress((void**)&wps, g_wps);
    cudaGetSymbolAddress((void**)&ob, g_ob);
    cudaGetSymbolAddress((void**)&os, g_os);

    cudaFuncSetAttribute(attn_mma, cudaFuncAttributeMaxDynamicSharedMemorySize, ATT_SMEM);
    cudaFuncSetAttribute(sgemm_bfx3, cudaFuncAttributeMaxDynamicSharedMemorySize, GSMEM);

    // 0) split fp32 -> permuted bf16 big/small pair arrays
    const int n4x = MTOT * DD / 4;
    const int n4q = 3 * DD * DD / 4;
    const int n4p = DD * DD / 4;
    split_bf16<<<(n4x + 255) / 256, 256>>>(x, xb, xs, n4x);
    split_bf16<<<(n4q + 255) / 256, 256>>>(w_qkv, wqb, wqs, n4q);
    split_bf16<<<(n4p + 255) / 256, 256>>>(w_proj, wpb, wps, n4p);

    // 1) qkv = x @ w_qkv^T   [bf16x3, cp.async pipelined]
    sgemm_bfx3<<<dim3(3 * DD / 128, MTOT / 128), 256, GSMEM>>>(xb, xs, wqb, wqs, qkv, MTOT, 3 * DD, KP);

    // 2) rmsnorm + rope + head split
    norm_rope_split<<<(MTOT * HH) / 8, 256>>>(qkv, rope, qw, kw, Q, K, V);

    // 3) attention -> fused split epilogue writes ob/os directly
    attn_mma<<<dim3(LL / 128, BB * HH), 256, ATT_SMEM>>>(Q, K, V, ob, os);

    // 4) out = O @ w_proj^T  [bf16x3]
    sgemm_bfx3<<<dim3(DD / 128, MTOT / 128), 256, GSMEM>>>(ob, os, wpb, wps, out, MTOT, DD, KP);
}